// round 10
// baseline (speedup 1.0000x reference)
#include <cuda_runtime.h>
#include <math.h>

#define BATCH  8
#define SEQ    577
#define DIM    768
#define HEADS  12
#define HDIM   64
#define MLPD   3072
#define DEPTH  8
#define NPATCH 576
#define PDIM   768
#define IMGH   384
#define PSZ    16
#define HP     24

// ---------------- scratch (device globals; allocation is banned) ------------
__device__ float g_X  [BATCH * SEQ * DIM];
__device__ float g_Y  [BATCH * SEQ * DIM];
__device__ float g_QKV[BATCH * SEQ * 3 * DIM];
__device__ float g_O  [BATCH * SEQ * DIM];
__device__ float g_H  [BATCH * SEQ * MLPD];
__device__ float g_P  [BATCH * NPATCH * PDIM];

// ---------------- tf32 helpers ----------------------------------------------
__device__ __forceinline__ unsigned f2tf(float f) {
    unsigned u;
    asm("cvt.rna.tf32.f32 %0, %1;" : "=r"(u) : "f"(f));
    return u;
}

#define MMA_TF32(d, a, b)                                                     \
    asm volatile("mma.sync.aligned.m16n8k8.row.col.f32.tf32.tf32.f32 "        \
                 "{%0,%1,%2,%3}, {%4,%5,%6,%7}, {%8,%9}, {%0,%1,%2,%3};\n"    \
                 : "+f"(d[0]), "+f"(d[1]), "+f"(d[2]), "+f"(d[3])             \
                 : "r"(a[0]), "r"(a[1]), "r"(a[2]), "r"(a[3]),                \
                   "r"(b[0]), "r"(b[1]))

// ---------------- generic batched tf32 tensor-core GEMM ----------------------
// BM=128 BN=64, 4x2 warps -> 32x32 warp tile, ~100 regs: fits 2 CTAs/SM
// unspilled under the forced (256,2) bound. Double-buffered smem, one sync
// per k-tile; register-staged LDGs; tf32 cvt once at smem-store time.
template<int BM, int BN, int BK, int WM, int WN>
__global__ void __launch_bounds__(WM * WN * 32, 2)
gemm_tc(const float* __restrict__ A, int lda, long long sAb, long long sAh, int vecA,
        const float* __restrict__ Bm, int ldb, long long sBb, long long sBh, int transB,
        const float* __restrict__ bias,
        float* __restrict__ C, int ldc, long long sCb, long long sCh,
        int M, int N, int K, int fuse)
{
    constexpr int NTHREADS = WM * WN * 32;
    constexpr int MT = (BM / WM) / 16;
    constexpr int NT = (BN / WN) / 8;
    constexpr int A_IT = BM * BK / (NTHREADS * 4);
    constexpr int B_IT = BK * BN / (NTHREADS * 4);
    constexpr int ASTR = BK + 4;          // conflict-free strides
    constexpr int BSTR = BN + 4;
    constexpr int ASZ = BM * ASTR;
    constexpr int BSZ = BK * BSTR;

    extern __shared__ unsigned gsm[];
    unsigned* AsBuf = gsm;
    unsigned* BsBuf = gsm + 2 * ASZ;

    int z  = blockIdx.z;
    int zb = z / HEADS, zh = z % HEADS;
    A  += zb * sAb + zh * sAh;
    Bm += zb * sBb + zh * sBh;
    C  += zb * sCb + zh * sCh;

    int r0 = blockIdx.y * BM;
    int c0 = blockIdx.x * BN;
    int tid  = threadIdx.x;
    int wid  = tid >> 5, lane = tid & 31;
    int wm   = wid / WN, wn = wid % WN;
    int q    = lane >> 2, r = lane & 3;

    float acc[MT][NT][4];
    #pragma unroll
    for (int i = 0; i < MT; i++)
        #pragma unroll
        for (int j = 0; j < NT; j++)
            #pragma unroll
            for (int t = 0; t < 4; t++) acc[i][j][t] = 0.f;

    float4 rA[A_IT], rB[B_IT];

    auto gloadA = [&](int k0) {
        #pragma unroll
        for (int it = 0; it < A_IT; it++) {
            int idx = (tid + it * NTHREADS) * 4;
            int m = idx / BK, kk = idx % BK;
            float4 v = make_float4(0.f, 0.f, 0.f, 0.f);
            if (r0 + m < M) {
                const float* p = A + (long long)(r0 + m) * lda + k0 + kk;
                if (vecA && k0 + kk + 3 < K) {
                    v = *(const float4*)p;
                } else {
                    if (k0 + kk     < K) v.x = p[0];
                    if (k0 + kk + 1 < K) v.y = p[1];
                    if (k0 + kk + 2 < K) v.z = p[2];
                    if (k0 + kk + 3 < K) v.w = p[3];
                }
            }
            rA[it] = v;
        }
    };
    auto gloadB = [&](int k0) {
        if (!transB) {
            #pragma unroll
            for (int it = 0; it < B_IT; it++) {
                int idx = (tid + it * NTHREADS) * 4;
                int kk = idx / BN, n = idx % BN;
                float4 v = make_float4(0.f, 0.f, 0.f, 0.f);
                if (k0 + kk < K) {
                    const float* p = Bm + (long long)(k0 + kk) * ldb + c0 + n;
                    if (c0 + n + 3 < N) {
                        v = *(const float4*)p;
                    } else {
                        if (c0 + n     < N) v.x = p[0];
                        if (c0 + n + 1 < N) v.y = p[1];
                        if (c0 + n + 2 < N) v.z = p[2];
                        if (c0 + n + 3 < N) v.w = p[3];
                    }
                }
                rB[it] = v;
            }
        } else {
            #pragma unroll
            for (int it = 0; it < B_IT; it++) {
                int idx = (tid + it * NTHREADS) * 4;
                int n = idx / BK, kk = idx % BK;
                float4 v = make_float4(0.f, 0.f, 0.f, 0.f);
                if (c0 + n < N) {
                    const float* p = Bm + (long long)(c0 + n) * ldb + k0 + kk;
                    if (k0 + kk + 3 < K) {
                        v = *(const float4*)p;
                    } else {
                        if (k0 + kk     < K) v.x = p[0];
                        if (k0 + kk + 1 < K) v.y = p[1];
                        if (k0 + kk + 2 < K) v.z = p[2];
                        if (k0 + kk + 3 < K) v.w = p[3];
                    }
                }
                rB[it] = v;
            }
        }
    };
    auto sstore = [&](int buf) {
        unsigned* As = AsBuf + buf * ASZ;
        unsigned* Bs = BsBuf + buf * BSZ;
        #pragma unroll
        for (int it = 0; it < A_IT; it++) {
            int idx = (tid + it * NTHREADS) * 4;
            int m = idx / BK, kk = idx % BK;
            As[m * ASTR + kk + 0] = f2tf(rA[it].x);
            As[m * ASTR + kk + 1] = f2tf(rA[it].y);
            As[m * ASTR + kk + 2] = f2tf(rA[it].z);
            As[m * ASTR + kk + 3] = f2tf(rA[it].w);
        }
        if (!transB) {
            #pragma unroll
            for (int it = 0; it < B_IT; it++) {
                int idx = (tid + it * NTHREADS) * 4;
                int kk = idx / BN, n = idx % BN;
                Bs[kk * BSTR + n + 0] = f2tf(rB[it].x);
                Bs[kk * BSTR + n + 1] = f2tf(rB[it].y);
                Bs[kk * BSTR + n + 2] = f2tf(rB[it].z);
                Bs[kk * BSTR + n + 3] = f2tf(rB[it].w);
            }
        } else {
            #pragma unroll
            for (int it = 0; it < B_IT; it++) {
                int idx = (tid + it * NTHREADS) * 4;
                int n = idx / BK, kk = idx % BK;
                Bs[(kk + 0) * BSTR + n] = f2tf(rB[it].x);
                Bs[(kk + 1) * BSTR + n] = f2tf(rB[it].y);
                Bs[(kk + 2) * BSTR + n] = f2tf(rB[it].z);
                Bs[(kk + 3) * BSTR + n] = f2tf(rB[it].w);
            }
        }
    };

    int T = (K + BK - 1) / BK;
    gloadA(0); gloadB(0);
    sstore(0);
    __syncthreads();

    for (int t = 0; t < T; t++) {
        if (t + 1 < T) {
            gloadA((t + 1) * BK);
            gloadB((t + 1) * BK);
        }
        const unsigned* As = AsBuf + (t & 1) * ASZ;
        const unsigned* Bs = BsBuf + (t & 1) * BSZ;

        #pragma unroll
        for (int kk = 0; kk < BK; kk += 8) {
            unsigned af[MT][4];
            unsigned bf[NT][2];
            #pragma unroll
            for (int i = 0; i < MT; i++) {
                int m = wm * (BM / WM) + i * 16;
                af[i][0] = As[(m + q    ) * ASTR + kk + r    ];
                af[i][1] = As[(m + q + 8) * ASTR + kk + r    ];
                af[i][2] = As[(m + q    ) * ASTR + kk + r + 4];
                af[i][3] = As[(m + q + 8) * ASTR + kk + r + 4];
            }
            #pragma unroll
            for (int j = 0; j < NT; j++) {
                int n = wn * (BN / WN) + j * 8;
                bf[j][0] = Bs[(kk + r    ) * BSTR + n + q];
                bf[j][1] = Bs[(kk + r + 4) * BSTR + n + q];
            }
            #pragma unroll
            for (int i = 0; i < MT; i++)
                #pragma unroll
                for (int j = 0; j < NT; j++)
                    MMA_TF32(acc[i][j], af[i], bf[j]);
        }

        if (t + 1 < T) {
            sstore((t + 1) & 1);
            __syncthreads();
        }
    }

    // ---- epilogue ----
    #pragma unroll
    for (int i = 0; i < MT; i++) {
        #pragma unroll
        for (int j = 0; j < NT; j++) {
            #pragma unroll
            for (int t = 0; t < 4; t++) {
                int row = r0 + wm * (BM / WM) + i * 16 + q + ((t >= 2) ? 8 : 0);
                int col = c0 + wn * (BN / WN) + j * 8 + r * 2 + (t & 1);
                if (row >= M || col >= N) continue;
                float v = acc[i][j][t];
                if (bias) v += bias[col];
                if (fuse == 1) v = 0.5f * v * (1.f + erff(v * 0.70710678118654752f));
                long long off = (long long)row * ldc + col;
                if (fuse == 2) v += C[off];
                C[off] = v;
            }
        }
    }
}

// ---------------- fused flash attention (round-8 proven) ----------------------
#define BQ   128
#define BKC  64
#define QSTR 68

__global__ void __launch_bounds__(256)
flash_attn_kernel(const float* __restrict__ QKV, float* __restrict__ O)
{
    extern __shared__ unsigned fa_sm[];
    unsigned* sQ = fa_sm;
    unsigned* sK = sQ + BQ  * QSTR;
    unsigned* sV = sK + BKC * QSTR;
    unsigned* sP = sV + BKC * QSTR;

    int z  = blockIdx.z;
    int b  = z / HEADS, h = z % HEADS;
    int q0 = blockIdx.y * BQ;

    const float* Qg = QKV + (long long)b * SEQ * (3 * DIM) + h * HDIM;
    const float* Kg = Qg + DIM;
    const float* Vg = Qg + 2 * DIM;

    int tid  = threadIdx.x;
    int wid  = tid >> 5, lane = tid & 31;
    int qr   = lane >> 2, r = lane & 3;
    int mrow = wid * 16;

    #pragma unroll
    for (int it = 0; it < BQ * HDIM / (256 * 4); it++) {
        int idx = (tid + it * 256) * 4;
        int m = idx / HDIM, d = idx % HDIM;
        float4 v = make_float4(0.f, 0.f, 0.f, 0.f);
        if (q0 + m < SEQ)
            v = *(const float4*)(Qg + (long long)(q0 + m) * (3 * DIM) + d);
        sQ[m * QSTR + d + 0] = f2tf(v.x);
        sQ[m * QSTR + d + 1] = f2tf(v.y);
        sQ[m * QSTR + d + 2] = f2tf(v.z);
        sQ[m * QSTR + d + 3] = f2tf(v.w);
    }

    float acc_O[8][4];
    #pragma unroll
    for (int j = 0; j < 8; j++)
        #pragma unroll
        for (int t = 0; t < 4; t++) acc_O[j][t] = 0.f;
    float mstate[2] = { -3.0e38f, -3.0e38f };
    float lstate[2] = { 0.f, 0.f };

    const int nchunks = (SEQ + BKC - 1) / BKC;
    for (int c = 0; c < nchunks; c++) {
        int kb = c * BKC;
        __syncthreads();

        #pragma unroll
        for (int it = 0; it < BKC * HDIM / (256 * 4); it++) {
            int idx = (tid + it * 256) * 4;
            int n = idx / HDIM, d = idx % HDIM;
            float4 v = make_float4(0.f, 0.f, 0.f, 0.f);
            if (kb + n < SEQ)
                v = *(const float4*)(Kg + (long long)(kb + n) * (3 * DIM) + d);
            sK[n * QSTR + d + 0] = f2tf(v.x);
            sK[n * QSTR + d + 1] = f2tf(v.y);
            sK[n * QSTR + d + 2] = f2tf(v.z);
            sK[n * QSTR + d + 3] = f2tf(v.w);
        }
        #pragma unroll
        for (int it = 0; it < BKC * HDIM / (256 * 4); it++) {
            int idx = (tid + it * 256) * 4;
            int n = idx / HDIM, d = idx % HDIM;
            float4 v = make_float4(0.f, 0.f, 0.f, 0.f);
            if (kb + n < SEQ)
                v = *(const float4*)(Vg + (long long)(kb + n) * (3 * DIM) + d);
            sV[n * QSTR + d + 0] = f2tf(v.x);
            sV[n * QSTR + d + 1] = f2tf(v.y);
            sV[n * QSTR + d + 2] = f2tf(v.z);
            sV[n * QSTR + d + 3] = f2tf(v.w);
        }
        __syncthreads();

        float acc_S[8][4];
        #pragma unroll
        for (int j = 0; j < 8; j++)
            #pragma unroll
            for (int t = 0; t < 4; t++) acc_S[j][t] = 0.f;

        #pragma unroll
        for (int kk = 0; kk < HDIM; kk += 8) {
            unsigned a[4] = { sQ[(mrow + qr    ) * QSTR + kk + r    ],
                              sQ[(mrow + qr + 8) * QSTR + kk + r    ],
                              sQ[(mrow + qr    ) * QSTR + kk + r + 4],
                              sQ[(mrow + qr + 8) * QSTR + kk + r + 4] };
            #pragma unroll
            for (int j = 0; j < 8; j++) {
                unsigned bb[2] = { sK[(j * 8 + qr) * QSTR + kk + r    ],
                                   sK[(j * 8 + qr) * QSTR + kk + r + 4] };
                MMA_TF32(acc_S[j], a, bb);
            }
        }

        float cmax[2] = { -3.0e38f, -3.0e38f };
        #pragma unroll
        for (int j = 0; j < 8; j++)
            #pragma unroll
            for (int t = 0; t < 4; t++) {
                int col = j * 8 + r * 2 + (t & 1);
                if (kb + col >= SEQ) acc_S[j][t] = -3.0e38f;
                cmax[t >> 1] = fmaxf(cmax[t >> 1], acc_S[j][t]);
            }
        #pragma unroll
        for (int o = 1; o <= 2; o <<= 1) {
            cmax[0] = fmaxf(cmax[0], __shfl_xor_sync(0xffffffffu, cmax[0], o));
            cmax[1] = fmaxf(cmax[1], __shfl_xor_sync(0xffffffffu, cmax[1], o));
        }
        float mnew[2]  = { fmaxf(mstate[0], cmax[0]), fmaxf(mstate[1], cmax[1]) };
        float scale[2] = { __expf(mstate[0] - mnew[0]), __expf(mstate[1] - mnew[1]) };
        float csum[2] = { 0.f, 0.f };
        #pragma unroll
        for (int j = 0; j < 8; j++)
            #pragma unroll
            for (int t = 0; t < 4; t++) {
                float p = __expf(acc_S[j][t] - mnew[t >> 1]);
                acc_S[j][t] = p;
                csum[t >> 1] += p;
            }
        #pragma unroll
        for (int o = 1; o <= 2; o <<= 1) {
            csum[0] += __shfl_xor_sync(0xffffffffu, csum[0], o);
            csum[1] += __shfl_xor_sync(0xffffffffu, csum[1], o);
        }
        lstate[0] = lstate[0] * scale[0] + csum[0];
        lstate[1] = lstate[1] * scale[1] + csum[1];
        mstate[0] = mnew[0];
        mstate[1] = mnew[1];
        #pragma unroll
        for (int j = 0; j < 8; j++)
            #pragma unroll
            for (int t = 0; t < 4; t++)
                acc_O[j][t] *= scale[t >> 1];

        #pragma unroll
        for (int j = 0; j < 8; j++)
            #pragma unroll
            for (int t = 0; t < 4; t++) {
                int row = mrow + qr + ((t >= 2) ? 8 : 0);
                int col = j * 8 + r * 2 + (t & 1);
                sP[row * QSTR + col] = f2tf(acc_S[j][t]);
            }
        __syncwarp();

        #pragma unroll
        for (int kk = 0; kk < BKC; kk += 8) {
            unsigned a[4] = { sP[(mrow + qr    ) * QSTR + kk + r    ],
                              sP[(mrow + qr + 8) * QSTR + kk + r    ],
                              sP[(mrow + qr    ) * QSTR + kk + r + 4],
                              sP[(mrow + qr + 8) * QSTR + kk + r + 4] };
            #pragma unroll
            for (int j = 0; j < 8; j++) {
                unsigned bb[2] = { sV[(kk + r    ) * QSTR + j * 8 + qr],
                                   sV[(kk + r + 4) * QSTR + j * 8 + qr] };
                MMA_TF32(acc_O[j], a, bb);
            }
        }
    }

    float inv[2] = { 1.f / lstate[0], 1.f / lstate[1] };
    #pragma unroll
    for (int j = 0; j < 8; j++)
        #pragma unroll
        for (int t = 0; t < 4; t++) {
            int row = q0 + mrow + qr + ((t >= 2) ? 8 : 0);
            int col = j * 8 + r * 2 + (t & 1);
            if (row < SEQ)
                O[((long long)b * SEQ + row) * DIM + h * HDIM + col] =
                    acc_O[j][t] * inv[t >> 1];
        }
}

// ---------------- reductions -------------------------------------------------
__device__ __forceinline__ float blockReduceSum(float v, volatile float* sh) {
    int lane = threadIdx.x & 31, w = threadIdx.x >> 5;
    #pragma unroll
    for (int o = 16; o; o >>= 1) v += __shfl_down_sync(0xffffffffu, v, o);
    if (lane == 0) sh[w] = v;
    __syncthreads();
    if (threadIdx.x < 32) {
        v = (threadIdx.x < 8) ? sh[threadIdx.x] : 0.f;
        #pragma unroll
        for (int o = 4; o; o >>= 1) v += __shfl_down_sync(0xffffffffu, v, o);
        if (lane == 0) sh[0] = v;
    }
    __syncthreads();
    return sh[0];
}

// ---------------- layernorm --------------------------------------------------
__global__ void __launch_bounds__(256)
layernorm_kernel(const float* __restrict__ X, const float* __restrict__ g,
                 const float* __restrict__ b, float* __restrict__ Y)
{
    long long row = blockIdx.x;
    const float* x = X + row * DIM;
    __shared__ float sh0[8], sh1[8];
    float v0 = x[threadIdx.x], v1 = x[threadIdx.x + 256], v2 = x[threadIdx.x + 512];
    float sum  = blockReduceSum(v0 + v1 + v2, sh0);
    float sum2 = blockReduceSum(v0 * v0 + v1 * v1 + v2 * v2, sh1);
    float m   = sum * (1.f / DIM);
    float var = sum2 * (1.f / DIM) - m * m;
    float inv = rsqrtf(var + 1e-5f);
    float* y = Y + row * DIM;
    #pragma unroll
    for (int i = 0; i < 3; i++) {
        int c = threadIdx.x + i * 256;
        float xv = (i == 0) ? v0 : (i == 1) ? v1 : v2;
        y[c] = (xv - m) * inv * g[c] + b[c];
    }
}

// ---------------- patchify ----------------------------------------------------
__global__ void __launch_bounds__(256)
patchify_kernel(const float* __restrict__ img)
{
    int idx = blockIdx.x * 256 + threadIdx.x;
    if (idx >= BATCH * NPATCH * PDIM) return;
    int pd = idx % PDIM;
    int t  = idx / PDIM;
    int patch = t % NPATCH;
    int b     = t / NPATCH;
    int c  = pd % 3;
    int pp = pd / 3;
    int p2 = pp % PSZ, p1 = pp / PSZ;
    int wx = patch % HP, hy = patch / HP;
    g_P[idx] = img[(((long long)b * 3 + c) * IMGH + hy * PSZ + p1) * IMGH + wx * PSZ + p2];
}

// ---------------- assemble: cls + pos add ------------------------------------
__global__ void __launch_bounds__(256)
assemble_kernel(const float* __restrict__ emb, const float* __restrict__ cls,
                const float* __restrict__ pos)
{
    int idx = blockIdx.x * 256 + threadIdx.x;
    if (idx >= BATCH * SEQ * DIM) return;
    int d = idx % DIM;
    int t = idx / DIM;
    int s = t % SEQ;
    int b = t / SEQ;
    float v;
    if (s == 0) v = cls[d] + pos[d];
    else        v = emb[((long long)b * NPATCH + (s - 1)) * DIM + d] + pos[(long long)s * DIM + d];
    g_X[idx] = v;
}

// ---------------- output: drop cls token -------------------------------------
__global__ void __launch_bounds__(256)
output_kernel(float* __restrict__ out)
{
    int idx = blockIdx.x * 256 + threadIdx.x;
    if (idx >= BATCH * NPATCH * DIM) return;
    int d = idx % DIM;
    int t = idx / DIM;
    int s = t % NPATCH;
    int b = t / NPATCH;
    out[idx] = g_X[((long long)b * SEQ + (s + 1)) * DIM + d];
}

// ---------------- host driver ------------------------------------------------
extern "C" void kernel_launch(void* const* d_in, const int* in_sizes, int n_in,
                              void* d_out, int out_size)
{
    const float* img   = (const float*)d_in[0];
    const float* pos   = (const float*)d_in[1];
    const float* cls   = (const float*)d_in[2];
    const float* pw    = (const float*)d_in[3];
    const float* pb    = (const float*)d_in[4];
    const float* ln1g  = (const float*)d_in[5];
    const float* ln1b  = (const float*)d_in[6];
    const float* qkvw  = (const float*)d_in[7];
    const float* outw  = (const float*)d_in[8];
    const float* outb  = (const float*)d_in[9];
    const float* ln2g  = (const float*)d_in[10];
    const float* ln2b  = (const float*)d_in[11];
    const float* ff1w  = (const float*)d_in[12];
    const float* ff1b  = (const float*)d_in[13];
    const float* ff2w  = (const float*)d_in[14];
    const float* ff2b  = (const float*)d_in[15];
    float* out = (float*)d_out;

    float *pX, *pY, *pQKV, *pO, *pH, *pP;
    cudaGetSymbolAddress((void**)&pX,   g_X);
    cudaGetSymbolAddress((void**)&pY,   g_Y);
    cudaGetSymbolAddress((void**)&pQKV, g_QKV);
    cudaGetSymbolAddress((void**)&pO,   g_O);
    cudaGetSymbolAddress((void**)&pH,   g_H);
    cudaGetSymbolAddress((void**)&pP,   g_P);

    const int Mfull = BATCH * SEQ;
    const int Mpat  = BATCH * NPATCH;

    // dynamic smem: 2 x (128*36 + 32*68) words = 54272 B -> 2 CTAs/SM
    const int SM_D = (2 * 128 * 36 + 2 * 32 * 68) * 4;
    const int FA_SMEM = (BQ + BKC + BKC + BQ) * QSTR * 4;  // 104448

    static int attr_done = 0;
    if (!attr_done) {
        cudaFuncSetAttribute((const void*)gemm_tc<128,64,32,4,2>,
                             cudaFuncAttributeMaxDynamicSharedMemorySize, SM_D);
        cudaFuncSetAttribute((const void*)flash_attn_kernel,
                             cudaFuncAttributeMaxDynamicSharedMemorySize, FA_SMEM);
        attr_done = 1;
    }

    auto grid = [](int M, int N, int Z) {
        return dim3((N + 63) / 64, (M + 127) / 128, Z);
    };

    // 1) patchify + patch embed + assemble
    patchify_kernel<<<(BATCH * NPATCH * PDIM + 255) / 256, 256>>>(img);
    gemm_tc<128,64,32,4,2><<<grid(Mpat, DIM, 1), 256, SM_D>>>(
        pP, PDIM, 0, 0, 1,  pw, DIM, 0, 0, 0,  pb,
        pY, DIM, 0, 0,  Mpat, DIM, PDIM, 0);
    assemble_kernel<<<(BATCH * SEQ * DIM + 255) / 256, 256>>>(pY, cls, pos);

    // 2) transformer layers
    for (int l = 0; l < DEPTH; l++) {
        const float* wqkv = qkvw + (long long)l * DIM * 3 * DIM;
        const float* wo   = outw + (long long)l * DIM * DIM;
        const float* bo   = outb + (long long)l * DIM;
        const float* w1   = ff1w + (long long)l * DIM * MLPD;
        const float* b1   = ff1b + (long long)l * MLPD;
        const float* w2   = ff2w + (long long)l * MLPD * DIM;
        const float* b2   = ff2b + (long long)l * DIM;

        layernorm_kernel<<<Mfull, 256>>>(pX, ln1g + (long long)l * DIM,
                                         ln1b + (long long)l * DIM, pY);
        gemm_tc<128,64,32,4,2><<<grid(Mfull, 3 * DIM, 1), 256, SM_D>>>(
            pY, DIM, 0, 0, 1,  wqkv, 3 * DIM, 0, 0, 0,  nullptr,
            pQKV, 3 * DIM, 0, 0,  Mfull, 3 * DIM, DIM, 0);
        {
            dim3 g(1, (SEQ + BQ - 1) / BQ, BATCH * HEADS);
            flash_attn_kernel<<<g, 256, FA_SMEM>>>(pQKV, pO);
        }
        gemm_tc<128,64,32,4,2><<<grid(Mfull, DIM, 1), 256, SM_D>>>(
            pO, DIM, 0, 0, 1,  wo, DIM, 0, 0, 0,  bo,
            pX, DIM, 0, 0,  Mfull, DIM, DIM, 2);
        layernorm_kernel<<<Mfull, 256>>>(pX, ln2g + (long long)l * DIM,
                                         ln2b + (long long)l * DIM, pY);
        gemm_tc<128,64,32,4,2><<<grid(Mfull, MLPD, 1), 256, SM_D>>>(
            pY, DIM, 0, 0, 1,  w1, MLPD, 0, 0, 0,  b1,
            pH, MLPD, 0, 0,  Mfull, MLPD, DIM, 1);
        gemm_tc<128,64,32,4,2><<<grid(Mfull, DIM, 1), 256, SM_D>>>(
            pH, MLPD, 0, 0, 1,  w2, DIM, 0, 0, 0,  b2,
            pX, DIM, 0, 0,  Mfull, DIM, MLPD, 2);
    }

    // 3) drop cls token -> output
    output_kernel<<<(BATCH * NPATCH * DIM + 255) / 256, 256>>>(out);
}

// round 11
// speedup vs baseline: 1.3711x; 1.3711x over previous
#include <cuda_runtime.h>
#include <cuda_fp16.h>
#include <math.h>

#define BATCH  8
#define SEQ    577
#define DIM    768
#define HEADS  12
#define HDIM   64
#define MLPD   3072
#define DEPTH  8
#define NPATCH 576
#define PDIM   768
#define IMGH   384
#define PSZ    16
#define HP     24

// ---------------- scratch (device globals; allocation is banned) ------------
__device__ float g_X  [BATCH * SEQ * DIM];
__device__ float g_Y  [BATCH * SEQ * DIM];
__device__ float g_QKV[BATCH * SEQ * 3 * DIM];
__device__ float g_O  [BATCH * SEQ * DIM];
__device__ float g_H  [BATCH * SEQ * MLPD];
__device__ float g_P  [BATCH * NPATCH * PDIM];

// ---------------- fp16 helpers ----------------------------------------------
__device__ __forceinline__ unsigned f2h2(float x, float y) {
    __half2 h = __floats2half2_rn(x, y);
    return *reinterpret_cast<unsigned*>(&h);
}

// D(f32) += A(f16) @ B(f16): m16n8k16. D-fragment layout identical to tf32 path.
#define MMA_F16(d, a, b)                                                      \
    asm volatile("mma.sync.aligned.m16n8k16.row.col.f32.f16.f16.f32 "         \
                 "{%0,%1,%2,%3}, {%4,%5,%6,%7}, {%8,%9}, {%0,%1,%2,%3};\n"    \
                 : "+f"(d[0]), "+f"(d[1]), "+f"(d[2]), "+f"(d[3])             \
                 : "r"(a[0]), "r"(a[1]), "r"(a[2]), "r"(a[3]),                \
                   "r"(b[0]), "r"(b[1]))

// ---------------- fp16 tensor-core GEMM (round-8 proven loop structure) ------
// C = op( A @ B (+ bias) ), fuse: 0=none, 1=gelu(exact), 2=residual add
// A row-major [M,K] (row-predicated); B row-major [K,N].
// Call-site invariants: K % BK == 0, N % BN == 0, 16B-aligned rows.
// Smem holds half2 words packed along k; fragment word-indexing mirrors the
// proven tf32 map exactly (a: kw+r / kw+r+4; b: word-row kw+r).
template<int BM, int BN, int BK, int WM, int WN>
__global__ void __launch_bounds__(WM * WN * 32)
gemm_tc(const float* __restrict__ A, int lda,
        const float* __restrict__ Bm, int ldb,
        const float* __restrict__ bias,
        float* __restrict__ C, int ldc,
        int M, int N, int K, int fuse)
{
    constexpr int NTHREADS = WM * WN * 32;
    constexpr int MT = (BM / WM) / 16;
    constexpr int NT = (BN / WN) / 8;
    constexpr int A_IT = BM * BK / (NTHREADS * 4);
    constexpr int B_IT = BK * BN / (NTHREADS * 4);
    constexpr int AW   = BK / 2;          // k-words per tile
    constexpr int ASTR = AW + 4;          // 20: banks (20q+r) conflict-free
    constexpr int BSTR = BN + 4;          // 132: banks (4r+q) conflict-free

    __shared__ unsigned As[BM * ASTR];    // [m][kw]
    __shared__ unsigned Bs[AW * BSTR];    // [kw][n]

    int r0 = blockIdx.y * BM;
    int c0 = blockIdx.x * BN;
    int tid  = threadIdx.x;
    int wid  = tid >> 5, lane = tid & 31;
    int wm   = wid / WN, wn = wid % WN;
    int q    = lane >> 2, r = lane & 3;

    float acc[MT][NT][4];
    #pragma unroll
    for (int i = 0; i < MT; i++)
        #pragma unroll
        for (int j = 0; j < NT; j++)
            #pragma unroll
            for (int t = 0; t < 4; t++) acc[i][j][t] = 0.f;

    float4 rA[A_IT], rB[B_IT];

    auto gloadA = [&](int k0) {
        #pragma unroll
        for (int it = 0; it < A_IT; it++) {
            int idx = (tid + it * NTHREADS) * 4;
            int m = idx / BK, kk = idx % BK;
            float4 v = make_float4(0.f, 0.f, 0.f, 0.f);
            if (r0 + m < M)
                v = *(const float4*)(A + (long long)(r0 + m) * lda + k0 + kk);
            rA[it] = v;
        }
    };
    auto gloadB = [&](int k0) {
        #pragma unroll
        for (int it = 0; it < B_IT; it++) {
            int idx = (tid + it * NTHREADS) * 4;
            int kk = idx / BN, n = idx % BN;
            rB[it] = *(const float4*)(Bm + (long long)(k0 + kk) * ldb + c0 + n);
        }
    };
    auto sstore = [&]() {
        #pragma unroll
        for (int it = 0; it < A_IT; it++) {
            int idx = (tid + it * NTHREADS) * 4;
            int m = idx / BK, kk = idx % BK;        // kk multiple of 4
            As[m * ASTR + (kk >> 1)    ] = f2h2(rA[it].x, rA[it].y);
            As[m * ASTR + (kk >> 1) + 1] = f2h2(rA[it].z, rA[it].w);
        }
        __half* Bh = (__half*)Bs;
        #pragma unroll
        for (int it = 0; it < B_IT; it++) {
            int idx = (tid + it * NTHREADS) * 4;
            int kk = idx / BN, n = idx % BN;
            int w = kk >> 1, par = kk & 1;
            int base = w * BSTR + n;
            Bh[((base + 0) << 1) | par] = __float2half_rn(rB[it].x);
            Bh[((base + 1) << 1) | par] = __float2half_rn(rB[it].y);
            Bh[((base + 2) << 1) | par] = __float2half_rn(rB[it].z);
            Bh[((base + 3) << 1) | par] = __float2half_rn(rB[it].w);
        }
    };

    int T = K / BK;
    gloadA(0); gloadB(0);

    for (int t = 0; t < T; t++) {
        sstore();
        __syncthreads();
        if (t + 1 < T) {
            gloadA((t + 1) * BK);
            gloadB((t + 1) * BK);
        }
        #pragma unroll
        for (int kw = 0; kw < AW; kw += 8) {        // k16 per step
            unsigned af[MT][4];
            unsigned bf[NT][2];
            #pragma unroll
            for (int i = 0; i < MT; i++) {
                int m = wm * (BM / WM) + i * 16;
                af[i][0] = As[(m + q    ) * ASTR + kw + r    ];
                af[i][1] = As[(m + q + 8) * ASTR + kw + r    ];
                af[i][2] = As[(m + q    ) * ASTR + kw + r + 4];
                af[i][3] = As[(m + q + 8) * ASTR + kw + r + 4];
            }
            #pragma unroll
            for (int j = 0; j < NT; j++) {
                int n = wn * (BN / WN) + j * 8;
                bf[j][0] = Bs[(kw + r    ) * BSTR + n + q];
                bf[j][1] = Bs[(kw + r + 4) * BSTR + n + q];
            }
            #pragma unroll
            for (int i = 0; i < MT; i++)
                #pragma unroll
                for (int j = 0; j < NT; j++)
                    MMA_F16(acc[i][j], af[i], bf[j]);
        }
        __syncthreads();
    }

    // ---- epilogue (unchanged fragment->C map) ----
    #pragma unroll
    for (int i = 0; i < MT; i++) {
        #pragma unroll
        for (int j = 0; j < NT; j++) {
            #pragma unroll
            for (int t = 0; t < 4; t++) {
                int row = r0 + wm * (BM / WM) + i * 16 + q + ((t >= 2) ? 8 : 0);
                int col = c0 + wn * (BN / WN) + j * 8 + r * 2 + (t & 1);
                if (row >= M) continue;
                float v = acc[i][j][t];
                if (bias) v += bias[col];
                if (fuse == 1) v = 0.5f * v * (1.f + erff(v * 0.70710678118654752f));
                long long off = (long long)row * ldc + col;
                if (fuse == 2) v += C[off];
                C[off] = v;
            }
        }
    }
}

// ---------------- fused flash attention (fp16 mma) ----------------------------
// Same structure/softmax as round-8; operands packed half2 along contraction.
#define BQ   128
#define BKC  64
#define DW   (HDIM / 2)       // 32 d-words
#define QSTRh (DW + 4)        // 36: banks (4q+r) conflict-free
#define VSTRh (HDIM + 4)      // 68: banks (4r+q) conflict-free
#define PW   (BKC / 2)        // 32 key-words
#define PSTRh (PW + 4)        // 36

__global__ void __launch_bounds__(256)
flash_attn_kernel(const float* __restrict__ QKV, float* __restrict__ O)
{
    extern __shared__ unsigned fa_sm[];
    unsigned* sQ = fa_sm;                  // [BQ ][QSTRh]  packed d-pairs
    unsigned* sK = sQ + BQ  * QSTRh;       // [BKC][QSTRh]  packed d-pairs
    unsigned* sV = sK + BKC * QSTRh;       // [PW ][VSTRh]  packed key-pairs
    unsigned* sP = sV + PW  * VSTRh;       // [BQ ][PSTRh]  packed key-pairs

    int z  = blockIdx.z;
    int b  = z / HEADS, h = z % HEADS;
    int q0 = blockIdx.y * BQ;

    const float* Qg = QKV + (long long)b * SEQ * (3 * DIM) + h * HDIM;
    const float* Kg = Qg + DIM;
    const float* Vg = Qg + 2 * DIM;

    int tid  = threadIdx.x;
    int wid  = tid >> 5, lane = tid & 31;
    int qr   = lane >> 2, r = lane & 3;
    int mrow = wid * 16;

    // ---- load Q tile once (d-pair packed words) ----
    #pragma unroll
    for (int it = 0; it < BQ * HDIM / (256 * 4); it++) {
        int idx = (tid + it * 256) * 4;
        int m = idx / HDIM, d = idx % HDIM;
        float4 v = make_float4(0.f, 0.f, 0.f, 0.f);
        if (q0 + m < SEQ)
            v = *(const float4*)(Qg + (long long)(q0 + m) * (3 * DIM) + d);
        sQ[m * QSTRh + (d >> 1)    ] = f2h2(v.x, v.y);
        sQ[m * QSTRh + (d >> 1) + 1] = f2h2(v.z, v.w);
    }

    float acc_O[8][4];
    #pragma unroll
    for (int j = 0; j < 8; j++)
        #pragma unroll
        for (int t = 0; t < 4; t++) acc_O[j][t] = 0.f;
    float mstate[2] = { -3.0e38f, -3.0e38f };
    float lstate[2] = { 0.f, 0.f };

    const int nchunks = (SEQ + BKC - 1) / BKC;
    for (int c = 0; c < nchunks; c++) {
        int kb = c * BKC;
        __syncthreads();

        // ---- K chunk [key][d-words] ----
        #pragma unroll
        for (int it = 0; it < BKC * HDIM / (256 * 4); it++) {
            int idx = (tid + it * 256) * 4;
            int n = idx / HDIM, d = idx % HDIM;
            float4 v = make_float4(0.f, 0.f, 0.f, 0.f);
            if (kb + n < SEQ)
                v = *(const float4*)(Kg + (long long)(kb + n) * (3 * DIM) + d);
            sK[n * QSTRh + (d >> 1)    ] = f2h2(v.x, v.y);
            sK[n * QSTRh + (d >> 1) + 1] = f2h2(v.z, v.w);
        }
        // ---- V chunk packed across key-pairs: word[kw][d] = {V[2kw][d], V[2kw+1][d]} ----
        {
            __half* Vh = (__half*)sV;
            #pragma unroll
            for (int it = 0; it < BKC * HDIM / (256 * 4); it++) {
                int idx = (tid + it * 256) * 4;
                int n = idx / HDIM, d = idx % HDIM;
                float4 v = make_float4(0.f, 0.f, 0.f, 0.f);
                if (kb + n < SEQ)
                    v = *(const float4*)(Vg + (long long)(kb + n) * (3 * DIM) + d);
                int w = n >> 1, par = n & 1;
                int base = w * VSTRh + d;
                Vh[((base + 0) << 1) | par] = __float2half_rn(v.x);
                Vh[((base + 1) << 1) | par] = __float2half_rn(v.y);
                Vh[((base + 2) << 1) | par] = __float2half_rn(v.z);
                Vh[((base + 3) << 1) | par] = __float2half_rn(v.w);
            }
        }
        __syncthreads();

        // ---- S = Q @ K^T (contraction over d: 4 k16 steps) ----
        float acc_S[8][4];
        #pragma unroll
        for (int j = 0; j < 8; j++)
            #pragma unroll
            for (int t = 0; t < 4; t++) acc_S[j][t] = 0.f;

        #pragma unroll
        for (int kw = 0; kw < DW; kw += 8) {
            unsigned a[4] = { sQ[(mrow + qr    ) * QSTRh + kw + r    ],
                              sQ[(mrow + qr + 8) * QSTRh + kw + r    ],
                              sQ[(mrow + qr    ) * QSTRh + kw + r + 4],
                              sQ[(mrow + qr + 8) * QSTRh + kw + r + 4] };
            #pragma unroll
            for (int j = 0; j < 8; j++) {
                unsigned bb[2] = { sK[(j * 8 + qr) * QSTRh + kw + r    ],
                                   sK[(j * 8 + qr) * QSTRh + kw + r + 4] };
                MMA_F16(acc_S[j], a, bb);
            }
        }

        // ---- mask invalid keys, online softmax (fp32, unchanged) ----
        float cmax[2] = { -3.0e38f, -3.0e38f };
        #pragma unroll
        for (int j = 0; j < 8; j++)
            #pragma unroll
            for (int t = 0; t < 4; t++) {
                int col = j * 8 + r * 2 + (t & 1);
                if (kb + col >= SEQ) acc_S[j][t] = -3.0e38f;
                cmax[t >> 1] = fmaxf(cmax[t >> 1], acc_S[j][t]);
            }
        #pragma unroll
        for (int o = 1; o <= 2; o <<= 1) {
            cmax[0] = fmaxf(cmax[0], __shfl_xor_sync(0xffffffffu, cmax[0], o));
            cmax[1] = fmaxf(cmax[1], __shfl_xor_sync(0xffffffffu, cmax[1], o));
        }
        float mnew[2]  = { fmaxf(mstate[0], cmax[0]), fmaxf(mstate[1], cmax[1]) };
        float scale[2] = { __expf(mstate[0] - mnew[0]), __expf(mstate[1] - mnew[1]) };
        float csum[2] = { 0.f, 0.f };
        #pragma unroll
        for (int j = 0; j < 8; j++)
            #pragma unroll
            for (int t = 0; t < 4; t++) {
                float p = __expf(acc_S[j][t] - mnew[t >> 1]);
                acc_S[j][t] = p;
                csum[t >> 1] += p;
            }
        #pragma unroll
        for (int o = 1; o <= 2; o <<= 1) {
            csum[0] += __shfl_xor_sync(0xffffffffu, csum[0], o);
            csum[1] += __shfl_xor_sync(0xffffffffu, csum[1], o);
        }
        lstate[0] = lstate[0] * scale[0] + csum[0];
        lstate[1] = lstate[1] * scale[1] + csum[1];
        mstate[0] = mnew[0];
        mstate[1] = mnew[1];
        #pragma unroll
        for (int j = 0; j < 8; j++)
            #pragma unroll
            for (int t = 0; t < 4; t++)
                acc_O[j][t] *= scale[t >> 1];

        // ---- P -> smem as packed key-pair words (cols r*2, r*2+1 are consecutive) ----
        #pragma unroll
        for (int j = 0; j < 8; j++) {
            sP[(mrow + qr    ) * PSTRh + j * 4 + r] = f2h2(acc_S[j][0], acc_S[j][1]);
            sP[(mrow + qr + 8) * PSTRh + j * 4 + r] = f2h2(acc_S[j][2], acc_S[j][3]);
        }
        __syncwarp();

        // ---- O += P @ V (contraction over keys: 4 k16 steps) ----
        #pragma unroll
        for (int kw = 0; kw < PW; kw += 8) {
            unsigned a[4] = { sP[(mrow + qr    ) * PSTRh + kw + r    ],
                              sP[(mrow + qr + 8) * PSTRh + kw + r    ],
                              sP[(mrow + qr    ) * PSTRh + kw + r + 4],
                              sP[(mrow + qr + 8) * PSTRh + kw + r + 4] };
            #pragma unroll
            for (int j = 0; j < 8; j++) {
                unsigned bb[2] = { sV[(kw + r    ) * VSTRh + j * 8 + qr],
                                   sV[(kw + r + 4) * VSTRh + j * 8 + qr] };
                MMA_F16(acc_O[j], a, bb);
            }
        }
    }

    // ---- epilogue: normalize, store ----
    float inv[2] = { 1.f / lstate[0], 1.f / lstate[1] };
    #pragma unroll
    for (int j = 0; j < 8; j++)
        #pragma unroll
        for (int t = 0; t < 4; t++) {
            int row = q0 + mrow + qr + ((t >= 2) ? 8 : 0);
            int col = j * 8 + r * 2 + (t & 1);
            if (row < SEQ)
                O[((long long)b * SEQ + row) * DIM + h * HDIM + col] =
                    acc_O[j][t] * inv[t >> 1];
        }
}

// ---------------- reductions -------------------------------------------------
__device__ __forceinline__ float blockReduceSum(float v, volatile float* sh) {
    int lane = threadIdx.x & 31, w = threadIdx.x >> 5;
    #pragma unroll
    for (int o = 16; o; o >>= 1) v += __shfl_down_sync(0xffffffffu, v, o);
    if (lane == 0) sh[w] = v;
    __syncthreads();
    if (threadIdx.x < 32) {
        v = (threadIdx.x < 8) ? sh[threadIdx.x] : 0.f;
        #pragma unroll
        for (int o = 4; o; o >>= 1) v += __shfl_down_sync(0xffffffffu, v, o);
        if (lane == 0) sh[0] = v;
    }
    __syncthreads();
    return sh[0];
}

// ---------------- layernorm --------------------------------------------------
__global__ void __launch_bounds__(256)
layernorm_kernel(const float* __restrict__ X, const float* __restrict__ g,
                 const float* __restrict__ b, float* __restrict__ Y)
{
    long long row = blockIdx.x;
    const float* x = X + row * DIM;
    __shared__ float sh0[8], sh1[8];
    float v0 = x[threadIdx.x], v1 = x[threadIdx.x + 256], v2 = x[threadIdx.x + 512];
    float sum  = blockReduceSum(v0 + v1 + v2, sh0);
    float sum2 = blockReduceSum(v0 * v0 + v1 * v1 + v2 * v2, sh1);
    float m   = sum * (1.f / DIM);
    float var = sum2 * (1.f / DIM) - m * m;
    float inv = rsqrtf(var + 1e-5f);
    float* y = Y + row * DIM;
    #pragma unroll
    for (int i = 0; i < 3; i++) {
        int c = threadIdx.x + i * 256;
        float xv = (i == 0) ? v0 : (i == 1) ? v1 : v2;
        y[c] = (xv - m) * inv * g[c] + b[c];
    }
}

// ---------------- patchify ----------------------------------------------------
__global__ void __launch_bounds__(256)
patchify_kernel(const float* __restrict__ img)
{
    int idx = blockIdx.x * 256 + threadIdx.x;
    if (idx >= BATCH * NPATCH * PDIM) return;
    int pd = idx % PDIM;
    int t  = idx / PDIM;
    int patch = t % NPATCH;
    int b     = t / NPATCH;
    int c  = pd % 3;
    int pp = pd / 3;
    int p2 = pp % PSZ, p1 = pp / PSZ;
    int wx = patch % HP, hy = patch / HP;
    g_P[idx] = img[(((long long)b * 3 + c) * IMGH + hy * PSZ + p1) * IMGH + wx * PSZ + p2];
}

// ---------------- assemble: cls + pos add ------------------------------------
__global__ void __launch_bounds__(256)
assemble_kernel(const float* __restrict__ emb, const float* __restrict__ cls,
                const float* __restrict__ pos)
{
    int idx = blockIdx.x * 256 + threadIdx.x;
    if (idx >= BATCH * SEQ * DIM) return;
    int d = idx % DIM;
    int t = idx / DIM;
    int s = t % SEQ;
    int b = t / SEQ;
    float v;
    if (s == 0) v = cls[d] + pos[d];
    else        v = emb[((long long)b * NPATCH + (s - 1)) * DIM + d] + pos[(long long)s * DIM + d];
    g_X[idx] = v;
}

// ---------------- output: drop cls token -------------------------------------
__global__ void __launch_bounds__(256)
output_kernel(float* __restrict__ out)
{
    int idx = blockIdx.x * 256 + threadIdx.x;
    if (idx >= BATCH * NPATCH * DIM) return;
    int d = idx % DIM;
    int t = idx / DIM;
    int s = t % NPATCH;
    int b = t / NPATCH;
    out[idx] = g_X[((long long)b * SEQ + (s + 1)) * DIM + d];
}

// ---------------- host driver ------------------------------------------------
extern "C" void kernel_launch(void* const* d_in, const int* in_sizes, int n_in,
                              void* d_out, int out_size)
{
    const float* img   = (const float*)d_in[0];
    const float* pos   = (const float*)d_in[1];
    const float* cls   = (const float*)d_in[2];
    const float* pw    = (const float*)d_in[3];
    const float* pb    = (const float*)d_in[4];
    const float* ln1g  = (const float*)d_in[5];
    const float* ln1b  = (const float*)d_in[6];
    const float* qkvw  = (const float*)d_in[7];
    const float* outw  = (const float*)d_in[8];
    const float* outb  = (const float*)d_in[9];
    const float* ln2g  = (const float*)d_in[10];
    const float* ln2b  = (const float*)d_in[11];
    const float* ff1w  = (const float*)d_in[12];
    const float* ff1b  = (const float*)d_in[13];
    const float* ff2w  = (const float*)d_in[14];
    const float* ff2b  = (const float*)d_in[15];
    float* out = (float*)d_out;

    float *pX, *pY, *pQKV, *pO, *pH, *pP;
    cudaGetSymbolAddress((void**)&pX,   g_X);
    cudaGetSymbolAddress((void**)&pY,   g_Y);
    cudaGetSymbolAddress((void**)&pQKV, g_QKV);
    cudaGetSymbolAddress((void**)&pO,   g_O);
    cudaGetSymbolAddress((void**)&pH,   g_H);
    cudaGetSymbolAddress((void**)&pP,   g_P);

    const int Mfull = BATCH * SEQ;
    const int Mpat  = BATCH * NPATCH;

    const int FA_SMEM = (BQ * QSTRh + BKC * QSTRh + PW * VSTRh + BQ * PSTRh) * 4; // 54784
    cudaFuncSetAttribute((const void*)flash_attn_kernel,
                         cudaFuncAttributeMaxDynamicSharedMemorySize, FA_SMEM);

    auto grid = [](int M, int N, int Z) {
        return dim3((N + 127) / 128, (M + 127) / 128, Z);
    };

    // 1) patchify + patch embed + assemble
    patchify_kernel<<<(BATCH * NPATCH * PDIM + 255) / 256, 256>>>(img);
    gemm_tc<128,128,32,2,4><<<grid(Mpat, DIM, 1), 256>>>(
        pP, PDIM,  pw, DIM,  pb,  pY, DIM,  Mpat, DIM, PDIM, 0);
    assemble_kernel<<<(BATCH * SEQ * DIM + 255) / 256, 256>>>(pY, cls, pos);

    // 2) transformer layers
    for (int l = 0; l < DEPTH; l++) {
        const float* wqkv = qkvw + (long long)l * DIM * 3 * DIM;
        const float* wo   = outw + (long long)l * DIM * DIM;
        const float* bo   = outb + (long long)l * DIM;
        const float* w1   = ff1w + (long long)l * DIM * MLPD;
        const float* b1   = ff1b + (long long)l * MLPD;
        const float* w2   = ff2w + (long long)l * MLPD * DIM;
        const float* b2   = ff2b + (long long)l * DIM;

        layernorm_kernel<<<Mfull, 256>>>(pX, ln1g + (long long)l * DIM,
                                         ln1b + (long long)l * DIM, pY);
        // QKV = Y @ Wqkv
        gemm_tc<128,128,32,2,4><<<grid(Mfull, 3 * DIM, 1), 256>>>(
            pY, DIM,  wqkv, 3 * DIM,  nullptr,  pQKV, 3 * DIM,
            Mfull, 3 * DIM, DIM, 0);
        // fused attention
        {
            dim3 g(1, (SEQ + BQ - 1) / BQ, BATCH * HEADS);
            flash_attn_kernel<<<g, 256, FA_SMEM>>>(pQKV, pO);
        }
        // X += O @ Wo + bo
        gemm_tc<128,128,32,2,4><<<grid(Mfull, DIM, 1), 256>>>(
            pO, DIM,  wo, DIM,  bo,  pX, DIM,  Mfull, DIM, DIM, 2);
        layernorm_kernel<<<Mfull, 256>>>(pX, ln2g + (long long)l * DIM,
                                         ln2b + (long long)l * DIM, pY);
        // H = gelu(Y @ W1 + b1)
        gemm_tc<128,128,32,2,4><<<grid(Mfull, MLPD, 1), 256>>>(
            pY, DIM,  w1, MLPD,  b1,  pH, MLPD,  Mfull, MLPD, DIM, 1);
        // X += H @ W2 + b2
        gemm_tc<128,128,32,2,4><<<grid(Mfull, DIM, 1), 256>>>(
            pH, MLPD,  w2, DIM,  b2,  pX, DIM,  Mfull, DIM, MLPD, 2);
    }

    // 3) drop cls token -> output
    output_kernel<<<(BATCH * NPATCH * DIM + 255) / 256, 256>>>(out);
}

// round 12
// speedup vs baseline: 1.5059x; 1.0983x over previous
#include <cuda_runtime.h>
#include <cuda_fp16.h>
#include <math.h>

#define BATCH  8
#define SEQ    577
#define DIM    768
#define HEADS  12
#define HDIM   64
#define MLPD   3072
#define DEPTH  8
#define NPATCH 576
#define PDIM   768
#define IMGH   384
#define PSZ    16
#define HP     24

// ---------------- scratch (device globals; allocation is banned) ------------
__device__ float g_X  [BATCH * SEQ * DIM];
__device__ float g_Y  [BATCH * SEQ * DIM];
__device__ float g_QKV[BATCH * SEQ * 3 * DIM];
__device__ float g_O  [BATCH * SEQ * DIM];
__device__ float g_H  [BATCH * SEQ * MLPD];
__device__ float g_P  [BATCH * NPATCH * PDIM];

// ---------------- fp16 helpers ----------------------------------------------
__device__ __forceinline__ unsigned f2h2(float x, float y) {
    __half2 h = __floats2half2_rn(x, y);
    return *reinterpret_cast<unsigned*>(&h);
}

#define MMA_F16(d, a, b)                                                      \
    asm volatile("mma.sync.aligned.m16n8k16.row.col.f32.f16.f16.f32 "         \
                 "{%0,%1,%2,%3}, {%4,%5,%6,%7}, {%8,%9}, {%0,%1,%2,%3};\n"    \
                 : "+f"(d[0]), "+f"(d[1]), "+f"(d[2]), "+f"(d[3])             \
                 : "r"(a[0]), "r"(a[1]), "r"(a[2]), "r"(a[3]),                \
                   "r"(b[0]), "r"(b[1]))

__device__ __forceinline__ void ldsm_x4(unsigned& d0, unsigned& d1,
                                        unsigned& d2, unsigned& d3,
                                        unsigned addr) {
    asm volatile("ldmatrix.sync.aligned.m8n8.x4.shared.b16 {%0,%1,%2,%3}, [%4];"
                 : "=r"(d0), "=r"(d1), "=r"(d2), "=r"(d3) : "r"(addr));
}
__device__ __forceinline__ void ldsm_x2(unsigned& d0, unsigned& d1,
                                        unsigned addr) {
    asm volatile("ldmatrix.sync.aligned.m8n8.x2.shared.b16 {%0,%1}, [%2];"
                 : "=r"(d0), "=r"(d1) : "r"(addr));
}

// ---------------- fp16 tensor-core GEMM (round-11 winner + ldmatrix A) -------
// C = op( A @ B (+ bias) ), fuse: 0=none, 1=gelu(exact), 2=residual add
// A row-major [M,K] (row-predicated); B row-major [K,N]. K%BK==0, N%BN==0.
template<int BM, int BN, int BK, int WM, int WN>
__global__ void __launch_bounds__(WM * WN * 32)
gemm_tc(const float* __restrict__ A, int lda,
        const float* __restrict__ Bm, int ldb,
        const float* __restrict__ bias,
        float* __restrict__ C, int ldc,
        int M, int N, int K, int fuse)
{
    constexpr int NTHREADS = WM * WN * 32;
    constexpr int MT = (BM / WM) / 16;
    constexpr int NT = (BN / WN) / 8;
    constexpr int A_IT = BM * BK / (NTHREADS * 4);
    constexpr int B_IT = BK * BN / (NTHREADS * 4);
    constexpr int AW   = BK / 2;
    constexpr int ASTR = AW + 4;          // 20 words: ldmatrix rows hit all banks
    constexpr int BSTR = BN + 4;          // 132: (4r+q) conflict-free

    __shared__ unsigned As[BM * ASTR];
    __shared__ unsigned Bs[AW * BSTR];

    int r0 = blockIdx.y * BM;
    int c0 = blockIdx.x * BN;
    int tid  = threadIdx.x;
    int wid  = tid >> 5, lane = tid & 31;
    int wm   = wid / WN, wn = wid % WN;
    int q    = lane >> 2, r = lane & 3;

    unsigned asBase = (unsigned)__cvta_generic_to_shared(As);
    // per-lane ldmatrix offset (bytes): T0/T1 rows 0-15 word kw, T2/T3 word kw+4
    unsigned aoff = (((lane & 15) * ASTR + (lane >> 4) * 4) << 2);

    float acc[MT][NT][4];
    #pragma unroll
    for (int i = 0; i < MT; i++)
        #pragma unroll
        for (int j = 0; j < NT; j++)
            #pragma unroll
            for (int t = 0; t < 4; t++) acc[i][j][t] = 0.f;

    float4 rA[A_IT], rB[B_IT];

    auto gloadA = [&](int k0) {
        #pragma unroll
        for (int it = 0; it < A_IT; it++) {
            int idx = (tid + it * NTHREADS) * 4;
            int m = idx / BK, kk = idx % BK;
            float4 v = make_float4(0.f, 0.f, 0.f, 0.f);
            if (r0 + m < M)
                v = *(const float4*)(A + (long long)(r0 + m) * lda + k0 + kk);
            rA[it] = v;
        }
    };
    auto gloadB = [&](int k0) {
        #pragma unroll
        for (int it = 0; it < B_IT; it++) {
            int idx = (tid + it * NTHREADS) * 4;
            int kk = idx / BN, n = idx % BN;
            rB[it] = *(const float4*)(Bm + (long long)(k0 + kk) * ldb + c0 + n);
        }
    };
    auto sstore = [&]() {
        #pragma unroll
        for (int it = 0; it < A_IT; it++) {
            int idx = (tid + it * NTHREADS) * 4;
            int m = idx / BK, kk = idx % BK;
            As[m * ASTR + (kk >> 1)    ] = f2h2(rA[it].x, rA[it].y);
            As[m * ASTR + (kk >> 1) + 1] = f2h2(rA[it].z, rA[it].w);
        }
        __half* Bh = (__half*)Bs;
        #pragma unroll
        for (int it = 0; it < B_IT; it++) {
            int idx = (tid + it * NTHREADS) * 4;
            int kk = idx / BN, n = idx % BN;
            int w = kk >> 1, par = kk & 1;
            int base = w * BSTR + n;
            Bh[((base + 0) << 1) | par] = __float2half_rn(rB[it].x);
            Bh[((base + 1) << 1) | par] = __float2half_rn(rB[it].y);
            Bh[((base + 2) << 1) | par] = __float2half_rn(rB[it].z);
            Bh[((base + 3) << 1) | par] = __float2half_rn(rB[it].w);
        }
    };

    int T = K / BK;
    gloadA(0); gloadB(0);

    for (int t = 0; t < T; t++) {
        sstore();
        __syncthreads();
        if (t + 1 < T) {
            gloadA((t + 1) * BK);
            gloadB((t + 1) * BK);
        }
        #pragma unroll
        for (int kw = 0; kw < AW; kw += 8) {
            unsigned af[MT][4];
            unsigned bf[NT][2];
            #pragma unroll
            for (int i = 0; i < MT; i++) {
                int m = wm * (BM / WM) + i * 16;
                ldsm_x4(af[i][0], af[i][1], af[i][2], af[i][3],
                        asBase + (((m * ASTR + kw) << 2)) + aoff);
            }
            #pragma unroll
            for (int j = 0; j < NT; j++) {
                int n = wn * (BN / WN) + j * 8;
                bf[j][0] = Bs[(kw + r    ) * BSTR + n + q];
                bf[j][1] = Bs[(kw + r + 4) * BSTR + n + q];
            }
            #pragma unroll
            for (int i = 0; i < MT; i++)
                #pragma unroll
                for (int j = 0; j < NT; j++)
                    MMA_F16(acc[i][j], af[i], bf[j]);
        }
        __syncthreads();
    }

    // ---- epilogue ----
    #pragma unroll
    for (int i = 0; i < MT; i++) {
        #pragma unroll
        for (int j = 0; j < NT; j++) {
            #pragma unroll
            for (int t = 0; t < 4; t++) {
                int row = r0 + wm * (BM / WM) + i * 16 + q + ((t >= 2) ? 8 : 0);
                int col = c0 + wn * (BN / WN) + j * 8 + r * 2 + (t & 1);
                if (row >= M) continue;
                float v = acc[i][j][t];
                if (bias) v += bias[col];
                if (fuse == 1) v = 0.5f * v * (1.f + erff(v * 0.70710678118654752f));
                long long off = (long long)row * ldc + col;
                if (fuse == 2) v += C[off];
                C[off] = v;
            }
        }
    }
}

// ---------------- fused flash attention (fp16 mma + ldmatrix) -----------------
#define BQ   128
#define BKC  64
#define DW   (HDIM / 2)
#define QSTRh (DW + 4)        // 36
#define VSTRh (HDIM + 4)      // 68
#define PW   (BKC / 2)
#define PSTRh (PW + 4)        // 36

__global__ void __launch_bounds__(256)
flash_attn_kernel(const float* __restrict__ QKV, float* __restrict__ O)
{
    extern __shared__ unsigned fa_sm[];
    unsigned* sQ = fa_sm;
    unsigned* sK = sQ + BQ  * QSTRh;
    unsigned* sV = sK + BKC * QSTRh;
    unsigned* sP = sV + PW  * VSTRh;

    int z  = blockIdx.z;
    int b  = z / HEADS, h = z % HEADS;
    int q0 = blockIdx.y * BQ;

    const float* Qg = QKV + (long long)b * SEQ * (3 * DIM) + h * HDIM;
    const float* Kg = Qg + DIM;
    const float* Vg = Qg + 2 * DIM;

    int tid  = threadIdx.x;
    int wid  = tid >> 5, lane = tid & 31;
    int qr   = lane >> 2, r = lane & 3;
    int mrow = wid * 16;

    unsigned sQb = (unsigned)__cvta_generic_to_shared(sQ);
    unsigned sKb = (unsigned)__cvta_generic_to_shared(sK);
    unsigned sPb = (unsigned)__cvta_generic_to_shared(sP);
    unsigned qoff = (((lane & 15) * QSTRh + (lane >> 4) * 4) << 2);
    unsigned koff = (((lane & 7)  * QSTRh + ((lane >> 3) & 1) * 4) << 2);
    unsigned poff = (((lane & 15) * PSTRh + (lane >> 4) * 4) << 2);

    #pragma unroll
    for (int it = 0; it < BQ * HDIM / (256 * 4); it++) {
        int idx = (tid + it * 256) * 4;
        int m = idx / HDIM, d = idx % HDIM;
        float4 v = make_float4(0.f, 0.f, 0.f, 0.f);
        if (q0 + m < SEQ)
            v = *(const float4*)(Qg + (long long)(q0 + m) * (3 * DIM) + d);
        sQ[m * QSTRh + (d >> 1)    ] = f2h2(v.x, v.y);
        sQ[m * QSTRh + (d >> 1) + 1] = f2h2(v.z, v.w);
    }

    float acc_O[8][4];
    #pragma unroll
    for (int j = 0; j < 8; j++)
        #pragma unroll
        for (int t = 0; t < 4; t++) acc_O[j][t] = 0.f;
    float mstate[2] = { -3.0e38f, -3.0e38f };
    float lstate[2] = { 0.f, 0.f };

    const int nchunks = (SEQ + BKC - 1) / BKC;
    for (int c = 0; c < nchunks; c++) {
        int kb = c * BKC;
        __syncthreads();

        #pragma unroll
        for (int it = 0; it < BKC * HDIM / (256 * 4); it++) {
            int idx = (tid + it * 256) * 4;
            int n = idx / HDIM, d = idx % HDIM;
            float4 v = make_float4(0.f, 0.f, 0.f, 0.f);
            if (kb + n < SEQ)
                v = *(const float4*)(Kg + (long long)(kb + n) * (3 * DIM) + d);
            sK[n * QSTRh + (d >> 1)    ] = f2h2(v.x, v.y);
            sK[n * QSTRh + (d >> 1) + 1] = f2h2(v.z, v.w);
        }
        {
            __half* Vh = (__half*)sV;
            #pragma unroll
            for (int it = 0; it < BKC * HDIM / (256 * 4); it++) {
                int idx = (tid + it * 256) * 4;
                int n = idx / HDIM, d = idx % HDIM;
                float4 v = make_float4(0.f, 0.f, 0.f, 0.f);
                if (kb + n < SEQ)
                    v = *(const float4*)(Vg + (long long)(kb + n) * (3 * DIM) + d);
                int w = n >> 1, par = n & 1;
                int base = w * VSTRh + d;
                Vh[((base + 0) << 1) | par] = __float2half_rn(v.x);
                Vh[((base + 1) << 1) | par] = __float2half_rn(v.y);
                Vh[((base + 2) << 1) | par] = __float2half_rn(v.z);
                Vh[((base + 3) << 1) | par] = __float2half_rn(v.w);
            }
        }
        __syncthreads();

        // ---- S = Q @ K^T ----
        float acc_S[8][4];
        #pragma unroll
        for (int j = 0; j < 8; j++)
            #pragma unroll
            for (int t = 0; t < 4; t++) acc_S[j][t] = 0.f;

        #pragma unroll
        for (int kw = 0; kw < DW; kw += 8) {
            unsigned a[4];
            ldsm_x4(a[0], a[1], a[2], a[3],
                    sQb + ((mrow * QSTRh + kw) << 2) + qoff);
            #pragma unroll
            for (int j = 0; j < 8; j++) {
                unsigned bb[2];
                ldsm_x2(bb[0], bb[1],
                        sKb + (((j * 8) * QSTRh + kw) << 2) + koff);
                MMA_F16(acc_S[j], a, bb);
            }
        }

        // ---- mask, online softmax ----
        float cmax[2] = { -3.0e38f, -3.0e38f };
        #pragma unroll
        for (int j = 0; j < 8; j++)
            #pragma unroll
            for (int t = 0; t < 4; t++) {
                int col = j * 8 + r * 2 + (t & 1);
                if (kb + col >= SEQ) acc_S[j][t] = -3.0e38f;
                cmax[t >> 1] = fmaxf(cmax[t >> 1], acc_S[j][t]);
            }
        #pragma unroll
        for (int o = 1; o <= 2; o <<= 1) {
            cmax[0] = fmaxf(cmax[0], __shfl_xor_sync(0xffffffffu, cmax[0], o));
            cmax[1] = fmaxf(cmax[1], __shfl_xor_sync(0xffffffffu, cmax[1], o));
        }
        float mnew[2]  = { fmaxf(mstate[0], cmax[0]), fmaxf(mstate[1], cmax[1]) };
        float scale[2] = { __expf(mstate[0] - mnew[0]), __expf(mstate[1] - mnew[1]) };
        float csum[2] = { 0.f, 0.f };
        #pragma unroll
        for (int j = 0; j < 8; j++)
            #pragma unroll
            for (int t = 0; t < 4; t++) {
                float p = __expf(acc_S[j][t] - mnew[t >> 1]);
                acc_S[j][t] = p;
                csum[t >> 1] += p;
            }
        #pragma unroll
        for (int o = 1; o <= 2; o <<= 1) {
            csum[0] += __shfl_xor_sync(0xffffffffu, csum[0], o);
            csum[1] += __shfl_xor_sync(0xffffffffu, csum[1], o);
        }
        lstate[0] = lstate[0] * scale[0] + csum[0];
        lstate[1] = lstate[1] * scale[1] + csum[1];
        mstate[0] = mnew[0];
        mstate[1] = mnew[1];
        #pragma unroll
        for (int j = 0; j < 8; j++)
            #pragma unroll
            for (int t = 0; t < 4; t++)
                acc_O[j][t] *= scale[t >> 1];

        // ---- P -> smem packed key-pairs ----
        #pragma unroll
        for (int j = 0; j < 8; j++) {
            sP[(mrow + qr    ) * PSTRh + j * 4 + r] = f2h2(acc_S[j][0], acc_S[j][1]);
            sP[(mrow + qr + 8) * PSTRh + j * 4 + r] = f2h2(acc_S[j][2], acc_S[j][3]);
        }
        __syncwarp();

        // ---- O += P @ V ----
        #pragma unroll
        for (int kw = 0; kw < PW; kw += 8) {
            unsigned a[4];
            ldsm_x4(a[0], a[1], a[2], a[3],
                    sPb + ((mrow * PSTRh + kw) << 2) + poff);
            #pragma unroll
            for (int j = 0; j < 8; j++) {
                unsigned bb[2] = { sV[(kw + r    ) * VSTRh + j * 8 + qr],
                                   sV[(kw + r + 4) * VSTRh + j * 8 + qr] };
                MMA_F16(acc_O[j], a, bb);
            }
        }
    }

    float inv[2] = { 1.f / lstate[0], 1.f / lstate[1] };
    #pragma unroll
    for (int j = 0; j < 8; j++)
        #pragma unroll
        for (int t = 0; t < 4; t++) {
            int row = q0 + mrow + qr + ((t >= 2) ? 8 : 0);
            int col = j * 8 + r * 2 + (t & 1);
            if (row < SEQ)
                O[((long long)b * SEQ + row) * DIM + h * HDIM + col] =
                    acc_O[j][t] * inv[t >> 1];
        }
}

// ---------------- reductions -------------------------------------------------
__device__ __forceinline__ float blockReduceSum(float v, volatile float* sh) {
    int lane = threadIdx.x & 31, w = threadIdx.x >> 5;
    #pragma unroll
    for (int o = 16; o; o >>= 1) v += __shfl_down_sync(0xffffffffu, v, o);
    if (lane == 0) sh[w] = v;
    __syncthreads();
    if (threadIdx.x < 32) {
        v = (threadIdx.x < 8) ? sh[threadIdx.x] : 0.f;
        #pragma unroll
        for (int o = 4; o; o >>= 1) v += __shfl_down_sync(0xffffffffu, v, o);
        if (lane == 0) sh[0] = v;
    }
    __syncthreads();
    return sh[0];
}

// ---------------- layernorm --------------------------------------------------
__global__ void __launch_bounds__(256)
layernorm_kernel(const float* __restrict__ X, const float* __restrict__ g,
                 const float* __restrict__ b, float* __restrict__ Y)
{
    long long row = blockIdx.x;
    const float* x = X + row * DIM;
    __shared__ float sh0[8], sh1[8];
    float v0 = x[threadIdx.x], v1 = x[threadIdx.x + 256], v2 = x[threadIdx.x + 512];
    float sum  = blockReduceSum(v0 + v1 + v2, sh0);
    float sum2 = blockReduceSum(v0 * v0 + v1 * v1 + v2 * v2, sh1);
    float m   = sum * (1.f / DIM);
    float var = sum2 * (1.f / DIM) - m * m;
    float inv = rsqrtf(var + 1e-5f);
    float* y = Y + row * DIM;
    #pragma unroll
    for (int i = 0; i < 3; i++) {
        int c = threadIdx.x + i * 256;
        float xv = (i == 0) ? v0 : (i == 1) ? v1 : v2;
        y[c] = (xv - m) * inv * g[c] + b[c];
    }
}

// ---------------- patchify ----------------------------------------------------
__global__ void __launch_bounds__(256)
patchify_kernel(const float* __restrict__ img)
{
    int idx = blockIdx.x * 256 + threadIdx.x;
    if (idx >= BATCH * NPATCH * PDIM) return;
    int pd = idx % PDIM;
    int t  = idx / PDIM;
    int patch = t % NPATCH;
    int b     = t / NPATCH;
    int c  = pd % 3;
    int pp = pd / 3;
    int p2 = pp % PSZ, p1 = pp / PSZ;
    int wx = patch % HP, hy = patch / HP;
    g_P[idx] = img[(((long long)b * 3 + c) * IMGH + hy * PSZ + p1) * IMGH + wx * PSZ + p2];
}

// ---------------- assemble: cls + pos add ------------------------------------
__global__ void __launch_bounds__(256)
assemble_kernel(const float* __restrict__ emb, const float* __restrict__ cls,
                const float* __restrict__ pos)
{
    int idx = blockIdx.x * 256 + threadIdx.x;
    if (idx >= BATCH * SEQ * DIM) return;
    int d = idx % DIM;
    int t = idx / DIM;
    int s = t % SEQ;
    int b = t / SEQ;
    float v;
    if (s == 0) v = cls[d] + pos[d];
    else        v = emb[((long long)b * NPATCH + (s - 1)) * DIM + d] + pos[(long long)s * DIM + d];
    g_X[idx] = v;
}

// ---------------- output: drop cls token -------------------------------------
__global__ void __launch_bounds__(256)
output_kernel(float* __restrict__ out)
{
    int idx = blockIdx.x * 256 + threadIdx.x;
    if (idx >= BATCH * NPATCH * DIM) return;
    int d = idx % DIM;
    int t = idx / DIM;
    int s = t % NPATCH;
    int b = t / NPATCH;
    out[idx] = g_X[((long long)b * SEQ + (s + 1)) * DIM + d];
}

// ---------------- host driver ------------------------------------------------
extern "C" void kernel_launch(void* const* d_in, const int* in_sizes, int n_in,
                              void* d_out, int out_size)
{
    const float* img   = (const float*)d_in[0];
    const float* pos   = (const float*)d_in[1];
    const float* cls   = (const float*)d_in[2];
    const float* pw    = (const float*)d_in[3];
    const float* pb    = (const float*)d_in[4];
    const float* ln1g  = (const float*)d_in[5];
    const float* ln1b  = (const float*)d_in[6];
    const float* qkvw  = (const float*)d_in[7];
    const float* outw  = (const float*)d_in[8];
    const float* outb  = (const float*)d_in[9];
    const float* ln2g  = (const float*)d_in[10];
    const float* ln2b  = (const float*)d_in[11];
    const float* ff1w  = (const float*)d_in[12];
    const float* ff1b  = (const float*)d_in[13];
    const float* ff2w  = (const float*)d_in[14];
    const float* ff2b  = (const float*)d_in[15];
    float* out = (float*)d_out;

    float *pX, *pY, *pQKV, *pO, *pH, *pP;
    cudaGetSymbolAddress((void**)&pX,   g_X);
    cudaGetSymbolAddress((void**)&pY,   g_Y);
    cudaGetSymbolAddress((void**)&pQKV, g_QKV);
    cudaGetSymbolAddress((void**)&pO,   g_O);
    cudaGetSymbolAddress((void**)&pH,   g_H);
    cudaGetSymbolAddress((void**)&pP,   g_P);

    const int Mfull = BATCH * SEQ;
    const int Mpat  = BATCH * NPATCH;

    const int FA_SMEM = (BQ * QSTRh + BKC * QSTRh + PW * VSTRh + BQ * PSTRh) * 4;
    cudaFuncSetAttribute((const void*)flash_attn_kernel,
                         cudaFuncAttributeMaxDynamicSharedMemorySize, FA_SMEM);

    auto grid = [](int M, int N, int Z) {
        return dim3((N + 127) / 128, (M + 127) / 128, Z);
    };

    // 1) patchify + patch embed + assemble
    patchify_kernel<<<(BATCH * NPATCH * PDIM + 255) / 256, 256>>>(img);
    gemm_tc<128,128,32,2,4><<<grid(Mpat, DIM, 1), 256>>>(
        pP, PDIM,  pw, DIM,  pb,  pY, DIM,  Mpat, DIM, PDIM, 0);
    assemble_kernel<<<(BATCH * SEQ * DIM + 255) / 256, 256>>>(pY, cls, pos);

    // 2) transformer layers
    for (int l = 0; l < DEPTH; l++) {
        const float* wqkv = qkvw + (long long)l * DIM * 3 * DIM;
        const float* wo   = outw + (long long)l * DIM * DIM;
        const float* bo   = outb + (long long)l * DIM;
        const float* w1   = ff1w + (long long)l * DIM * MLPD;
        const float* b1   = ff1b + (long long)l * MLPD;
        const float* w2   = ff2w + (long long)l * MLPD * DIM;
        const float* b2   = ff2b + (long long)l * DIM;

        layernorm_kernel<<<Mfull, 256>>>(pX, ln1g + (long long)l * DIM,
                                         ln1b + (long long)l * DIM, pY);
        gemm_tc<128,128,32,2,4><<<grid(Mfull, 3 * DIM, 1), 256>>>(
            pY, DIM,  wqkv, 3 * DIM,  nullptr,  pQKV, 3 * DIM,
            Mfull, 3 * DIM, DIM, 0);
        {
            dim3 g(1, (SEQ + BQ - 1) / BQ, BATCH * HEADS);
            flash_attn_kernel<<<g, 256, FA_SMEM>>>(pQKV, pO);
        }
        gemm_tc<128,128,32,2,4><<<grid(Mfull, DIM, 1), 256>>>(
            pO, DIM,  wo, DIM,  bo,  pX, DIM,  Mfull, DIM, DIM, 2);
        layernorm_kernel<<<Mfull, 256>>>(pX, ln2g + (long long)l * DIM,
                                         ln2b + (long long)l * DIM, pY);
        gemm_tc<128,128,32,2,4><<<grid(Mfull, MLPD, 1), 256>>>(
            pY, DIM,  w1, MLPD,  b1,  pH, MLPD,  Mfull, MLPD, DIM, 1);
        gemm_tc<128,128,32,2,4><<<grid(Mfull, DIM, 1), 256>>>(
            pH, MLPD,  w2, DIM,  b2,  pX, DIM,  Mfull, DIM, MLPD, 2);
    }

    // 3) drop cls token -> output
    output_kernel<<<(BATCH * NPATCH * DIM + 255) / 256, 256>>>(out);
}

// round 13
// speedup vs baseline: 1.5582x; 1.0348x over previous
#include <cuda_runtime.h>
#include <cuda_fp16.h>
#include <math.h>

#define BATCH  8
#define SEQ    577
#define DIM    768
#define HEADS  12
#define HDIM   64
#define MLPD   3072
#define DEPTH  8
#define NPATCH 576
#define PDIM   768
#define IMGH   384
#define PSZ    16
#define HP     24

// fp16 weight buffer offsets (in halfs)
#define OFF_PW   0
#define SZ_PW    (PDIM * DIM)                    // 589824
#define OFF_QKV  (OFF_PW + SZ_PW)
#define SZ_QKV   (DEPTH * DIM * 3 * DIM)         // 14155776
#define OFF_OUT  (OFF_QKV + SZ_QKV)
#define SZ_OUT   (DEPTH * DIM * DIM)             // 4718592
#define OFF_FF1  (OFF_OUT + SZ_OUT)
#define SZ_FF1   (DEPTH * DIM * MLPD)            // 18874368
#define OFF_FF2  (OFF_FF1 + SZ_FF1)
#define SZ_FF2   (DEPTH * MLPD * DIM)            // 18874368
#define W16_TOTAL (OFF_FF2 + SZ_FF2)             // 57212928

// ---------------- scratch (device globals; allocation is banned) ------------
__device__ float  g_X   [BATCH * SEQ * DIM];       // residual (fp32)
__device__ float  g_Yf  [BATCH * SEQ * DIM];       // patch-embed tmp (fp32)
__device__ __half g_Yh  [BATCH * SEQ * DIM];       // LN output (fp16)
__device__ __half g_QKVh[BATCH * SEQ * 3 * DIM];   // qkv (fp16)
__device__ __half g_Oh  [BATCH * SEQ * DIM];       // attn out (fp16)
__device__ __half g_Hh  [BATCH * SEQ * MLPD];      // mlp hidden (fp16)
__device__ __half g_Ph  [BATCH * NPATCH * PDIM];   // patches (fp16)
__device__ __half g_W16 [W16_TOTAL];               // fp16 weights

// ---------------- helpers ----------------------------------------------------
#define MMA_F16(d, a, b)                                                      \
    asm volatile("mma.sync.aligned.m16n8k16.row.col.f32.f16.f16.f32 "         \
                 "{%0,%1,%2,%3}, {%4,%5,%6,%7}, {%8,%9}, {%0,%1,%2,%3};\n"    \
                 : "+f"(d[0]), "+f"(d[1]), "+f"(d[2]), "+f"(d[3])             \
                 : "r"(a[0]), "r"(a[1]), "r"(a[2]), "r"(a[3]),                \
                   "r"(b[0]), "r"(b[1]))

__device__ __forceinline__ void ldsm_x4(unsigned& d0, unsigned& d1,
                                        unsigned& d2, unsigned& d3,
                                        unsigned addr) {
    asm volatile("ldmatrix.sync.aligned.m8n8.x4.shared.b16 {%0,%1,%2,%3}, [%4];"
                 : "=r"(d0), "=r"(d1), "=r"(d2), "=r"(d3) : "r"(addr));
}

// ---------------- weight fp32 -> fp16 conversion ------------------------------
__global__ void __launch_bounds__(256)
f2h_kernel(const float* __restrict__ s, __half* __restrict__ d, int n)
{
    int i = blockIdx.x * 256 + threadIdx.x;
    int stride = gridDim.x * 256;
    for (; i < n; i += stride) d[i] = __float2half_rn(s[i]);
}

// ---------------- fp16-in tensor-core GEMM (round-12 winner structure) -------
// C = op( A @ B (+ bias) ). A half row-major [M,K] (row-pred), B half [K,N].
// Output: Ch!=null -> fp16 store; else fp32 (fuse==2 adds residual).
// fuse: 0=none, 1=gelu(exact), 2=residual add. K%BK==0, N%BN==0, rows 16B-aligned.
template<int BM, int BN, int BK, int WM, int WN>
__global__ void __launch_bounds__(WM * WN * 32)
gemm_tc(const __half* __restrict__ A, int lda,
        const __half* __restrict__ Bm, int ldb,
        const float* __restrict__ bias,
        float* __restrict__ C, __half* __restrict__ Ch, int ldc,
        int M, int N, int K, int fuse)
{
    constexpr int NTHREADS = WM * WN * 32;
    constexpr int MT = (BM / WM) / 16;
    constexpr int NT = (BN / WN) / 8;
    constexpr int A_IT = BM * BK / (NTHREADS * 8);   // uint4 = 8 halfs
    constexpr int B_IT = BK * BN / (NTHREADS * 8);
    constexpr int AW   = BK / 2;
    constexpr int ASTR = AW + 4;          // 20 words: proven conflict-free
    constexpr int BSTR = BN + 4;          // 132 words: proven conflict-free

    __shared__ unsigned As[BM * ASTR];
    __shared__ unsigned Bs[AW * BSTR];

    int r0 = blockIdx.y * BM;
    int c0 = blockIdx.x * BN;
    int tid  = threadIdx.x;
    int wid  = tid >> 5, lane = tid & 31;
    int wm   = wid / WN, wn = wid % WN;
    int q    = lane >> 2, r = lane & 3;

    unsigned asBase = (unsigned)__cvta_generic_to_shared(As);
    unsigned aoff = (((lane & 15) * ASTR + (lane >> 4) * 4) << 2);

    float acc[MT][NT][4];
    #pragma unroll
    for (int i = 0; i < MT; i++)
        #pragma unroll
        for (int j = 0; j < NT; j++)
            #pragma unroll
            for (int t = 0; t < 4; t++) acc[i][j][t] = 0.f;

    uint4 rA[A_IT], rB[B_IT];

    auto gloadA = [&](int k0) {
        #pragma unroll
        for (int it = 0; it < A_IT; it++) {
            int idx = (tid + it * NTHREADS) * 8;
            int m = idx / BK, kk = idx % BK;
            uint4 v = make_uint4(0u, 0u, 0u, 0u);
            if (r0 + m < M)
                v = *(const uint4*)(A + (long long)(r0 + m) * lda + k0 + kk);
            rA[it] = v;
        }
    };
    auto gloadB = [&](int k0) {
        #pragma unroll
        for (int it = 0; it < B_IT; it++) {
            int idx = (tid + it * NTHREADS) * 8;
            int kk = idx / BN, n = idx % BN;
            rB[it] = *(const uint4*)(Bm + (long long)(k0 + kk) * ldb + c0 + n);
        }
    };
    auto sstore = [&]() {
        // A: contiguous k-halfs -> single 16B smem store
        #pragma unroll
        for (int it = 0; it < A_IT; it++) {
            int idx = (tid + it * NTHREADS) * 8;
            int m = idx / BK, kk = idx % BK;
            *(uint4*)&As[m * ASTR + (kk >> 1)] = rA[it];
        }
        // B: parity-pack halves along k (proven word layout, no conversion)
        __half* Bh = (__half*)Bs;
        #pragma unroll
        for (int it = 0; it < B_IT; it++) {
            int idx = (tid + it * NTHREADS) * 8;
            int kk = idx / BN, n = idx % BN;
            int w = kk >> 1, par = kk & 1;
            const __half* hv = (const __half*)&rB[it];
            int base = w * BSTR + n;
            #pragma unroll
            for (int i = 0; i < 8; i++)
                Bh[((base + i) << 1) | par] = hv[i];
        }
    };

    int T = K / BK;
    gloadA(0); gloadB(0);

    for (int t = 0; t < T; t++) {
        sstore();
        __syncthreads();
        if (t + 1 < T) {
            gloadA((t + 1) * BK);
            gloadB((t + 1) * BK);
        }
        #pragma unroll
        for (int kw = 0; kw < AW; kw += 8) {
            unsigned af[MT][4];
            unsigned bf[NT][2];
            #pragma unroll
            for (int i = 0; i < MT; i++) {
                int m = wm * (BM / WM) + i * 16;
                ldsm_x4(af[i][0], af[i][1], af[i][2], af[i][3],
                        asBase + (((m * ASTR + kw) << 2)) + aoff);
            }
            #pragma unroll
            for (int j = 0; j < NT; j++) {
                int n = wn * (BN / WN) + j * 8;
                bf[j][0] = Bs[(kw + r    ) * BSTR + n + q];
                bf[j][1] = Bs[(kw + r + 4) * BSTR + n + q];
            }
            #pragma unroll
            for (int i = 0; i < MT; i++)
                #pragma unroll
                for (int j = 0; j < NT; j++)
                    MMA_F16(acc[i][j], af[i], bf[j]);
        }
        __syncthreads();
    }

    // ---- epilogue ----
    #pragma unroll
    for (int i = 0; i < MT; i++) {
        #pragma unroll
        for (int j = 0; j < NT; j++) {
            #pragma unroll
            for (int t = 0; t < 4; t++) {
                int row = r0 + wm * (BM / WM) + i * 16 + q + ((t >= 2) ? 8 : 0);
                int col = c0 + wn * (BN / WN) + j * 8 + r * 2 + (t & 1);
                if (row >= M) continue;
                float v = acc[i][j][t];
                if (bias) v += bias[col];
                if (fuse == 1) v = 0.5f * v * (1.f + erff(v * 0.70710678118654752f));
                long long off = (long long)row * ldc + col;
                if (Ch) {
                    Ch[off] = __float2half_rn(v);
                } else {
                    if (fuse == 2) v += C[off];
                    C[off] = v;
                }
            }
        }
    }
}

// ---------------- fused flash attention (fp16 in/out) -------------------------
#define BQ   128
#define BKC  64
#define DW   (HDIM / 2)
#define QSTRh (DW + 4)        // 36
#define VSTRh (HDIM + 4)      // 68
#define PW   (BKC / 2)
#define PSTRh (PW + 4)        // 36

__device__ __forceinline__ unsigned f2h2(float x, float y) {
    __half2 h = __floats2half2_rn(x, y);
    return *reinterpret_cast<unsigned*>(&h);
}

__global__ void __launch_bounds__(256)
flash_attn_kernel(const __half* __restrict__ QKV, __half* __restrict__ O)
{
    extern __shared__ unsigned fa_sm[];
    unsigned* sQ = fa_sm;
    unsigned* sK = sQ + BQ  * QSTRh;
    unsigned* sV = sK + BKC * QSTRh;
    unsigned* sP = sV + PW  * VSTRh;

    int z  = blockIdx.z;
    int b  = z / HEADS, h = z % HEADS;
    int q0 = blockIdx.y * BQ;

    const __half* Qg = QKV + (long long)b * SEQ * (3 * DIM) + h * HDIM;
    const __half* Kg = Qg + DIM;
    const __half* Vg = Qg + 2 * DIM;

    int tid  = threadIdx.x;
    int wid  = tid >> 5, lane = tid & 31;
    int qr   = lane >> 2, r = lane & 3;
    int mrow = wid * 16;

    unsigned sQb = (unsigned)__cvta_generic_to_shared(sQ);
    unsigned sKb = (unsigned)__cvta_generic_to_shared(sK);
    unsigned sPb = (unsigned)__cvta_generic_to_shared(sP);
    unsigned qoff = (((lane & 15) * QSTRh + (lane >> 4) * 4) << 2);
    unsigned koff = (((lane & 7)  * QSTRh + ((lane >> 3) & 1) * 4) << 2);
    unsigned poff = (((lane & 15) * PSTRh + (lane >> 4) * 4) << 2);

    // ---- Q tile: direct uint4 copies (global halfs are already d-pair packed)
    #pragma unroll
    for (int it = 0; it < BQ * HDIM / (256 * 8); it++) {
        int idx = (tid + it * 256) * 8;
        int m = idx / HDIM, d = idx % HDIM;
        uint4 v = make_uint4(0u, 0u, 0u, 0u);
        if (q0 + m < SEQ)
            v = *(const uint4*)(Qg + (long long)(q0 + m) * (3 * DIM) + d);
        *(uint4*)&sQ[m * QSTRh + (d >> 1)] = v;
    }

    float acc_O[8][4];
    #pragma unroll
    for (int j = 0; j < 8; j++)
        #pragma unroll
        for (int t = 0; t < 4; t++) acc_O[j][t] = 0.f;
    float mstate[2] = { -3.0e38f, -3.0e38f };
    float lstate[2] = { 0.f, 0.f };

    const int nchunks = (SEQ + BKC - 1) / BKC;
    for (int c = 0; c < nchunks; c++) {
        int kb = c * BKC;
        __syncthreads();

        #pragma unroll
        for (int it = 0; it < BKC * HDIM / (256 * 8); it++) {
            int idx = (tid + it * 256) * 8;
            int n = idx / HDIM, d = idx % HDIM;
            uint4 v = make_uint4(0u, 0u, 0u, 0u);
            if (kb + n < SEQ)
                v = *(const uint4*)(Kg + (long long)(kb + n) * (3 * DIM) + d);
            *(uint4*)&sK[n * QSTRh + (d >> 1)] = v;
        }
        {
            __half* Vh = (__half*)sV;
            #pragma unroll
            for (int it = 0; it < BKC * HDIM / (256 * 8); it++) {
                int idx = (tid + it * 256) * 8;
                int n = idx / HDIM, d = idx % HDIM;
                uint4 v = make_uint4(0u, 0u, 0u, 0u);
                if (kb + n < SEQ)
                    v = *(const uint4*)(Vg + (long long)(kb + n) * (3 * DIM) + d);
                const __half* hv = (const __half*)&v;
                int w = n >> 1, par = n & 1;
                int base = w * VSTRh + d;
                #pragma unroll
                for (int i = 0; i < 8; i++)
                    Vh[((base + i) << 1) | par] = hv[i];
            }
        }
        __syncthreads();

        // ---- S = Q @ K^T ----
        float acc_S[8][4];
        #pragma unroll
        for (int j = 0; j < 8; j++)
            #pragma unroll
            for (int t = 0; t < 4; t++) acc_S[j][t] = 0.f;

        #pragma unroll
        for (int kw = 0; kw < DW; kw += 8) {
            unsigned a[4];
            ldsm_x4(a[0], a[1], a[2], a[3],
                    sQb + ((mrow * QSTRh + kw) << 2) + qoff);
            #pragma unroll
            for (int j = 0; j < 8; j++) {
                unsigned bb[2];
                asm volatile("ldmatrix.sync.aligned.m8n8.x2.shared.b16 {%0,%1}, [%2];"
                             : "=r"(bb[0]), "=r"(bb[1])
                             : "r"(sKb + (((j * 8) * QSTRh + kw) << 2) + koff));
                MMA_F16(acc_S[j], a, bb);
            }
        }

        // ---- mask, online softmax ----
        float cmax[2] = { -3.0e38f, -3.0e38f };
        #pragma unroll
        for (int j = 0; j < 8; j++)
            #pragma unroll
            for (int t = 0; t < 4; t++) {
                int col = j * 8 + r * 2 + (t & 1);
                if (kb + col >= SEQ) acc_S[j][t] = -3.0e38f;
                cmax[t >> 1] = fmaxf(cmax[t >> 1], acc_S[j][t]);
            }
        #pragma unroll
        for (int o = 1; o <= 2; o <<= 1) {
            cmax[0] = fmaxf(cmax[0], __shfl_xor_sync(0xffffffffu, cmax[0], o));
            cmax[1] = fmaxf(cmax[1], __shfl_xor_sync(0xffffffffu, cmax[1], o));
        }
        float mnew[2]  = { fmaxf(mstate[0], cmax[0]), fmaxf(mstate[1], cmax[1]) };
        float scale[2] = { __expf(mstate[0] - mnew[0]), __expf(mstate[1] - mnew[1]) };
        float csum[2] = { 0.f, 0.f };
        #pragma unroll
        for (int j = 0; j < 8; j++)
            #pragma unroll
            for (int t = 0; t < 4; t++) {
                float p = __expf(acc_S[j][t] - mnew[t >> 1]);
                acc_S[j][t] = p;
                csum[t >> 1] += p;
            }
        #pragma unroll
        for (int o = 1; o <= 2; o <<= 1) {
            csum[0] += __shfl_xor_sync(0xffffffffu, csum[0], o);
            csum[1] += __shfl_xor_sync(0xffffffffu, csum[1], o);
        }
        lstate[0] = lstate[0] * scale[0] + csum[0];
        lstate[1] = lstate[1] * scale[1] + csum[1];
        mstate[0] = mnew[0];
        mstate[1] = mnew[1];
        #pragma unroll
        for (int j = 0; j < 8; j++)
            #pragma unroll
            for (int t = 0; t < 4; t++)
                acc_O[j][t] *= scale[t >> 1];

        // ---- P -> smem packed key-pairs ----
        #pragma unroll
        for (int j = 0; j < 8; j++) {
            sP[(mrow + qr    ) * PSTRh + j * 4 + r] = f2h2(acc_S[j][0], acc_S[j][1]);
            sP[(mrow + qr + 8) * PSTRh + j * 4 + r] = f2h2(acc_S[j][2], acc_S[j][3]);
        }
        __syncwarp();

        // ---- O += P @ V ----
        #pragma unroll
        for (int kw = 0; kw < PW; kw += 8) {
            unsigned a[4];
            ldsm_x4(a[0], a[1], a[2], a[3],
                    sPb + ((mrow * PSTRh + kw) << 2) + poff);
            #pragma unroll
            for (int j = 0; j < 8; j++) {
                unsigned bb[2] = { sV[(kw + r    ) * VSTRh + j * 8 + qr],
                                   sV[(kw + r + 4) * VSTRh + j * 8 + qr] };
                MMA_F16(acc_O[j], a, bb);
            }
        }
    }

    float inv[2] = { 1.f / lstate[0], 1.f / lstate[1] };
    #pragma unroll
    for (int j = 0; j < 8; j++)
        #pragma unroll
        for (int t = 0; t < 4; t++) {
            int row = q0 + mrow + qr + ((t >= 2) ? 8 : 0);
            int col = j * 8 + r * 2 + (t & 1);
            if (row < SEQ)
                O[((long long)b * SEQ + row) * DIM + h * HDIM + col] =
                    __float2half_rn(acc_O[j][t] * inv[t >> 1]);
        }
}

// ---------------- reductions -------------------------------------------------
__device__ __forceinline__ float blockReduceSum(float v, volatile float* sh) {
    int lane = threadIdx.x & 31, w = threadIdx.x >> 5;
    #pragma unroll
    for (int o = 16; o; o >>= 1) v += __shfl_down_sync(0xffffffffu, v, o);
    if (lane == 0) sh[w] = v;
    __syncthreads();
    if (threadIdx.x < 32) {
        v = (threadIdx.x < 8) ? sh[threadIdx.x] : 0.f;
        #pragma unroll
        for (int o = 4; o; o >>= 1) v += __shfl_down_sync(0xffffffffu, v, o);
        if (lane == 0) sh[0] = v;
    }
    __syncthreads();
    return sh[0];
}

// ---------------- layernorm (fp32 in, fp16 out) -------------------------------
__global__ void __launch_bounds__(256)
layernorm_kernel(const float* __restrict__ X, const float* __restrict__ g,
                 const float* __restrict__ b, __half* __restrict__ Y)
{
    long long row = blockIdx.x;
    const float* x = X + row * DIM;
    __shared__ float sh0[8], sh1[8];
    float v0 = x[threadIdx.x], v1 = x[threadIdx.x + 256], v2 = x[threadIdx.x + 512];
    float sum  = blockReduceSum(v0 + v1 + v2, sh0);
    float sum2 = blockReduceSum(v0 * v0 + v1 * v1 + v2 * v2, sh1);
    float m   = sum * (1.f / DIM);
    float var = sum2 * (1.f / DIM) - m * m;
    float inv = rsqrtf(var + 1e-5f);
    __half* y = Y + row * DIM;
    #pragma unroll
    for (int i = 0; i < 3; i++) {
        int c = threadIdx.x + i * 256;
        float xv = (i == 0) ? v0 : (i == 1) ? v1 : v2;
        y[c] = __float2half_rn((xv - m) * inv * g[c] + b[c]);
    }
}

// ---------------- patchify (fp16 out) -----------------------------------------
__global__ void __launch_bounds__(256)
patchify_kernel(const float* __restrict__ img)
{
    int idx = blockIdx.x * 256 + threadIdx.x;
    if (idx >= BATCH * NPATCH * PDIM) return;
    int pd = idx % PDIM;
    int t  = idx / PDIM;
    int patch = t % NPATCH;
    int b     = t / NPATCH;
    int c  = pd % 3;
    int pp = pd / 3;
    int p2 = pp % PSZ, p1 = pp / PSZ;
    int wx = patch % HP, hy = patch / HP;
    g_Ph[idx] = __float2half_rn(
        img[(((long long)b * 3 + c) * IMGH + hy * PSZ + p1) * IMGH + wx * PSZ + p2]);
}

// ---------------- assemble: cls + pos add (fp32) ------------------------------
__global__ void __launch_bounds__(256)
assemble_kernel(const float* __restrict__ emb, const float* __restrict__ cls,
                const float* __restrict__ pos)
{
    int idx = blockIdx.x * 256 + threadIdx.x;
    if (idx >= BATCH * SEQ * DIM) return;
    int d = idx % DIM;
    int t = idx / DIM;
    int s = t % SEQ;
    int b = t / SEQ;
    float v;
    if (s == 0) v = cls[d] + pos[d];
    else        v = emb[((long long)b * NPATCH + (s - 1)) * DIM + d] + pos[(long long)s * DIM + d];
    g_X[idx] = v;
}

// ---------------- output: drop cls token --------------------------------------
__global__ void __launch_bounds__(256)
output_kernel(float* __restrict__ out)
{
    int idx = blockIdx.x * 256 + threadIdx.x;
    if (idx >= BATCH * NPATCH * DIM) return;
    int d = idx % DIM;
    int t = idx / DIM;
    int s = t % NPATCH;
    int b = t / NPATCH;
    out[idx] = g_X[((long long)b * SEQ + (s + 1)) * DIM + d];
}

// ---------------- host driver -------------------------------------------------
extern "C" void kernel_launch(void* const* d_in, const int* in_sizes, int n_in,
                              void* d_out, int out_size)
{
    const float* img   = (const float*)d_in[0];
    const float* pos   = (const float*)d_in[1];
    const float* cls   = (const float*)d_in[2];
    const float* pw    = (const float*)d_in[3];
    const float* pb    = (const float*)d_in[4];
    const float* ln1g  = (const float*)d_in[5];
    const float* ln1b  = (const float*)d_in[6];
    const float* qkvw  = (const float*)d_in[7];
    const float* outw  = (const float*)d_in[8];
    const float* outb  = (const float*)d_in[9];
    const float* ln2g  = (const float*)d_in[10];
    const float* ln2b  = (const float*)d_in[11];
    const float* ff1w  = (const float*)d_in[12];
    const float* ff1b  = (const float*)d_in[13];
    const float* ff2w  = (const float*)d_in[14];
    const float* ff2b  = (const float*)d_in[15];
    float* out = (float*)d_out;

    float  *pX, *pYf;
    __half *pYh, *pQKV, *pO, *pH, *pP, *pW;
    cudaGetSymbolAddress((void**)&pX,   g_X);
    cudaGetSymbolAddress((void**)&pYf,  g_Yf);
    cudaGetSymbolAddress((void**)&pYh,  g_Yh);
    cudaGetSymbolAddress((void**)&pQKV, g_QKVh);
    cudaGetSymbolAddress((void**)&pO,   g_Oh);
    cudaGetSymbolAddress((void**)&pH,   g_Hh);
    cudaGetSymbolAddress((void**)&pP,   g_Ph);
    cudaGetSymbolAddress((void**)&pW,   g_W16);

    const int Mfull = BATCH * SEQ;
    const int Mpat  = BATCH * NPATCH;

    const int FA_SMEM = (BQ * QSTRh + BKC * QSTRh + PW * VSTRh + BQ * PSTRh) * 4;
    cudaFuncSetAttribute((const void*)flash_attn_kernel,
                         cudaFuncAttributeMaxDynamicSharedMemorySize, FA_SMEM);

    auto grid = [](int M, int N, int Z) {
        return dim3((N + 127) / 128, (M + 127) / 128, Z);
    };
    auto cgrid = [](int n) { int g = (n + 255) / 256; return g > 4096 ? 4096 : g; };

    // 0) convert weights to fp16 (every call; deterministic, graph-capturable)
    f2h_kernel<<<cgrid(SZ_PW),  256>>>(pw,   pW + OFF_PW,  SZ_PW);
    f2h_kernel<<<cgrid(SZ_QKV), 256>>>(qkvw, pW + OFF_QKV, SZ_QKV);
    f2h_kernel<<<cgrid(SZ_OUT), 256>>>(outw, pW + OFF_OUT, SZ_OUT);
    f2h_kernel<<<cgrid(SZ_FF1), 256>>>(ff1w, pW + OFF_FF1, SZ_FF1);
    f2h_kernel<<<cgrid(SZ_FF2), 256>>>(ff2w, pW + OFF_FF2, SZ_FF2);

    // 1) patchify + patch embed + assemble
    patchify_kernel<<<(BATCH * NPATCH * PDIM + 255) / 256, 256>>>(img);
    gemm_tc<128,128,32,2,4><<<grid(Mpat, DIM, 1), 256>>>(
        pP, PDIM,  pW + OFF_PW, DIM,  pb,
        pYf, nullptr, DIM,  Mpat, DIM, PDIM, 0);
    assemble_kernel<<<(BATCH * SEQ * DIM + 255) / 256, 256>>>(pYf, cls, pos);

    // 2) transformer layers
    for (int l = 0; l < DEPTH; l++) {
        const __half* wqkv = pW + OFF_QKV + (long long)l * DIM * 3 * DIM;
        const __half* wo   = pW + OFF_OUT + (long long)l * DIM * DIM;
        const __half* w1   = pW + OFF_FF1 + (long long)l * DIM * MLPD;
        const __half* w2   = pW + OFF_FF2 + (long long)l * MLPD * DIM;
        const float* bo = outb + (long long)l * DIM;
        const float* b1 = ff1b + (long long)l * MLPD;
        const float* b2 = ff2b + (long long)l * DIM;

        layernorm_kernel<<<Mfull, 256>>>(pX, ln1g + (long long)l * DIM,
                                         ln1b + (long long)l * DIM, pYh);
        // QKV = Y @ Wqkv  (fp16 out)
        gemm_tc<128,128,32,2,4><<<grid(Mfull, 3 * DIM, 1), 256>>>(
            pYh, DIM,  wqkv, 3 * DIM,  nullptr,
            nullptr, pQKV, 3 * DIM,  Mfull, 3 * DIM, DIM, 0);
        // fused attention (fp16 in/out)
        {
            dim3 g(1, (SEQ + BQ - 1) / BQ, BATCH * HEADS);
            flash_attn_kernel<<<g, 256, FA_SMEM>>>(pQKV, pO);
        }
        // X += O @ Wo + bo  (fp32 residual)
        gemm_tc<128,128,32,2,4><<<grid(Mfull, DIM, 1), 256>>>(
            pO, DIM,  wo, DIM,  bo,
            pX, nullptr, DIM,  Mfull, DIM, DIM, 2);
        layernorm_kernel<<<Mfull, 256>>>(pX, ln2g + (long long)l * DIM,
                                         ln2b + (long long)l * DIM, pYh);
        // H = gelu(Y @ W1 + b1)  (fp16 out)
        gemm_tc<128,128,32,2,4><<<grid(Mfull, MLPD, 1), 256>>>(
            pYh, DIM,  w1, MLPD,  b1,
            nullptr, pH, MLPD,  Mfull, MLPD, DIM, 1);
        // X += H @ W2 + b2  (fp32 residual)
        gemm_tc<128,128,32,2,4><<<grid(Mfull, DIM, 1), 256>>>(
            pH, MLPD,  w2, DIM,  b2,
            pX, nullptr, DIM,  Mfull, DIM, MLPD, 2);
    }

    // 3) drop cls token -> output
    output_kernel<<<(BATCH * NPATCH * DIM + 255) / 256, 256>>>(out);
}

// round 14
// speedup vs baseline: 2.1608x; 1.3867x over previous
#include <cuda_runtime.h>
#include <cuda_fp16.h>
#include <math.h>
#include <stdint.h>

#define BATCH  8
#define SEQ    577
#define DIM    768
#define HEADS  12
#define HDIM   64
#define MLPD   3072
#define DEPTH  8
#define NPATCH 576
#define PDIM   768
#define IMGH   384
#define PSZ    16
#define HP     24

// fp16 weight buffer offsets (in halfs)
#define OFF_PW   0
#define SZ_PW    (PDIM * DIM)
#define OFF_QKV  (OFF_PW + SZ_PW)
#define SZ_QKV   (DEPTH * DIM * 3 * DIM)
#define OFF_OUT  (OFF_QKV + SZ_QKV)
#define SZ_OUT   (DEPTH * DIM * DIM)
#define OFF_FF1  (OFF_OUT + SZ_OUT)
#define SZ_FF1   (DEPTH * DIM * MLPD)
#define OFF_FF2  (OFF_FF1 + SZ_FF1)
#define SZ_FF2   (DEPTH * MLPD * DIM)
#define W16_TOTAL (OFF_FF2 + SZ_FF2)

// ---------------- scratch (device globals; allocation is banned) ------------
__device__ float  g_X   [BATCH * SEQ * DIM];
__device__ float  g_Yf  [BATCH * SEQ * DIM];
__device__ __half g_Yh  [BATCH * SEQ * DIM];
__device__ __half g_QKVh[BATCH * SEQ * 3 * DIM];
__device__ __half g_Oh  [BATCH * SEQ * DIM];
__device__ __half g_Hh  [BATCH * SEQ * MLPD];
__device__ __half g_Ph  [BATCH * NPATCH * PDIM];
__device__ __half g_W16 [W16_TOTAL];

// ---------------- helpers ----------------------------------------------------
#define MMA_F16(d, a, b)                                                      \
    asm volatile("mma.sync.aligned.m16n8k16.row.col.f32.f16.f16.f32 "         \
                 "{%0,%1,%2,%3}, {%4,%5,%6,%7}, {%8,%9}, {%0,%1,%2,%3};\n"    \
                 : "+f"(d[0]), "+f"(d[1]), "+f"(d[2]), "+f"(d[3])             \
                 : "r"(a[0]), "r"(a[1]), "r"(a[2]), "r"(a[3]),                \
                   "r"(b[0]), "r"(b[1]))

__device__ __forceinline__ void ldsm_x4(unsigned& d0, unsigned& d1,
                                        unsigned& d2, unsigned& d3,
                                        unsigned addr) {
    asm volatile("ldmatrix.sync.aligned.m8n8.x4.shared.b16 {%0,%1,%2,%3}, [%4];"
                 : "=r"(d0), "=r"(d1), "=r"(d2), "=r"(d3) : "r"(addr));
}
__device__ __forceinline__ void ldsm_x4t(unsigned& d0, unsigned& d1,
                                         unsigned& d2, unsigned& d3,
                                         unsigned addr) {
    asm volatile("ldmatrix.sync.aligned.m8n8.x4.trans.shared.b16 {%0,%1,%2,%3}, [%4];"
                 : "=r"(d0), "=r"(d1), "=r"(d2), "=r"(d3) : "r"(addr));
}

__device__ __forceinline__ void cpa16(unsigned saddr, const void* gptr, bool pred) {
    int sz = pred ? 16 : 0;
    asm volatile("cp.async.cg.shared.global [%0], [%1], 16, %2;\n"
                 :: "r"(saddr), "l"(gptr), "r"(sz));
}
#define CP_COMMIT() asm volatile("cp.async.commit_group;\n" ::: "memory")
#define CP_WAIT(n)  asm volatile("cp.async.wait_group %0;\n" :: "n"(n) : "memory")

// ---------------- weight fp32 -> fp16 conversion ------------------------------
__global__ void __launch_bounds__(256)
f2h_kernel(const float* __restrict__ s, __half* __restrict__ d, int n)
{
    int i = blockIdx.x * 256 + threadIdx.x;
    int stride = gridDim.x * 256;
    for (; i < n; i += stride) d[i] = __float2half_rn(s[i]);
}

// ---------------- fp16 tensor-core GEMM: cp.async + ldmatrix(.trans) ---------
// C = op( A @ B (+ bias) ). A half [M,K] row-major (row-pred), B half [K,N].
// Output: Ch!=null -> fp16; else fp32 (fuse==2 residual add).
// Invariants: K%BK==0, N%BN==0, 16B-aligned rows.
template<int BM, int BN, int BK, int WM, int WN>
__global__ void __launch_bounds__(WM * WN * 32)
gemm_tc(const __half* __restrict__ A, int lda,
        const __half* __restrict__ Bm, int ldb,
        const float* __restrict__ bias,
        float* __restrict__ C, __half* __restrict__ Ch, int ldc,
        int M, int N, int K, int fuse)
{
    constexpr int NTHREADS = WM * WN * 32;
    constexpr int MT = (BM / WM) / 16;
    constexpr int NT = (BN / WN) / 8;
    constexpr int A_IT = BM * BK / (NTHREADS * 8);
    constexpr int B_IT = BK * BN / (NTHREADS * 8);
    constexpr int AW   = BK / 2;          // A k-words per tile
    constexpr int ASTR = AW + 4;          // 20 words
    constexpr int BSTR = BN / 2 + 4;      // 68 words: trans-ldsm banks (4k+c), floor-only
    constexpr int ASZ = BM * ASTR;
    constexpr int BSZ = BK * BSTR;

    __shared__ unsigned As[2 * ASZ];
    __shared__ unsigned Bs[2 * BSZ];

    int r0 = blockIdx.y * BM;
    int c0 = blockIdx.x * BN;
    int tid  = threadIdx.x;
    int wid  = tid >> 5, lane = tid & 31;
    int wm   = wid / WN, wn = wid % WN;
    int q    = lane >> 2, r = lane & 3;

    unsigned asBase = (unsigned)__cvta_generic_to_shared(As);
    unsigned bsBase = (unsigned)__cvta_generic_to_shared(Bs);
    // A ldmatrix per-lane offset (bytes)
    unsigned aoff = (((lane & 15) * ASTR + (lane >> 4) * 4) << 2);
    // B trans-ldmatrix per-lane offset: mi=lane>>3; rows k_local, col block n_off
    {
    }
    int mi = lane >> 3;
    int k_local = (lane & 7) + (mi & 1) * 8;
    int n_off_w = (mi >> 1) * 4;          // 8 halfs = 4 words
    unsigned boff = ((k_local * BSTR + n_off_w) << 2);

    float acc[MT][NT][4];
    #pragma unroll
    for (int i = 0; i < MT; i++)
        #pragma unroll
        for (int j = 0; j < NT; j++)
            #pragma unroll
            for (int t = 0; t < 4; t++) acc[i][j][t] = 0.f;

    auto loadTile = [&](int k0, int buf) {
        // A tile: rows of BK halfs; 16B chunks
        #pragma unroll
        for (int it = 0; it < A_IT; it++) {
            int idx = (tid + it * NTHREADS) * 8;
            int m = idx / BK, kk = idx % BK;
            bool p = (r0 + m) < M;
            int row = p ? (r0 + m) : 0;
            cpa16(asBase + ((buf * ASZ + m * ASTR + (kk >> 1)) << 2),
                  A + (long long)row * lda + k0 + kk, p);
        }
        // B tile: [k][n] natural rows; 16B chunks
        #pragma unroll
        for (int it = 0; it < B_IT; it++) {
            int idx = (tid + it * NTHREADS) * 8;
            int kk = idx / BN, n = idx % BN;
            cpa16(bsBase + ((buf * BSZ + kk * BSTR + (n >> 1)) << 2),
                  Bm + (long long)(k0 + kk) * ldb + c0 + n, true);
        }
        CP_COMMIT();
    };

    int T = K / BK;
    loadTile(0, 0);

    for (int t = 0; t < T; t++) {
        if (t + 1 < T) {
            loadTile((t + 1) * BK, (t + 1) & 1);
            CP_WAIT(1);
        } else {
            CP_WAIT(0);
        }
        __syncthreads();

        unsigned aB = asBase + ((t & 1) * ASZ << 2);
        unsigned bB = bsBase + ((t & 1) * BSZ << 2);
        int nb_w = wn * (BN / WN) / 2;    // warp n-base in words

        #pragma unroll
        for (int kw = 0; kw < AW; kw += 8) {
            unsigned af[MT][4];
            unsigned bf[NT][2];
            #pragma unroll
            for (int i = 0; i < MT; i++) {
                int m = wm * (BM / WM) + i * 16;
                ldsm_x4(af[i][0], af[i][1], af[i][2], af[i][3],
                        aB + ((m * ASTR + kw) << 2) + aoff);
            }
            int kk = kw * 2;              // half-index of this k16 step
            #pragma unroll
            for (int jj = 0; jj < NT / 2; jj++) {
                ldsm_x4t(bf[2 * jj][0], bf[2 * jj][1],
                         bf[2 * jj + 1][0], bf[2 * jj + 1][1],
                         bB + ((kk * BSTR + nb_w + jj * 8) << 2) + boff);
            }
            #pragma unroll
            for (int i = 0; i < MT; i++)
                #pragma unroll
                for (int j = 0; j < NT; j++)
                    MMA_F16(acc[i][j], af[i], bf[j]);
        }
        __syncthreads();
    }

    // ---- epilogue ----
    #pragma unroll
    for (int i = 0; i < MT; i++) {
        #pragma unroll
        for (int j = 0; j < NT; j++) {
            #pragma unroll
            for (int t = 0; t < 4; t++) {
                int row = r0 + wm * (BM / WM) + i * 16 + q + ((t >= 2) ? 8 : 0);
                int col = c0 + wn * (BN / WN) + j * 8 + r * 2 + (t & 1);
                if (row >= M) continue;
                float v = acc[i][j][t];
                if (bias) v += bias[col];
                if (fuse == 1) v = 0.5f * v * (1.f + erff(v * 0.70710678118654752f));
                long long off = (long long)row * ldc + col;
                if (Ch) {
                    Ch[off] = __float2half_rn(v);
                } else {
                    if (fuse == 2) v += C[off];
                    C[off] = v;
                }
            }
        }
    }
}

// ---------------- fused flash attention (round-13 proven) ---------------------
#define BQ   128
#define BKC  64
#define DW   (HDIM / 2)
#define QSTRh (DW + 4)
#define VSTRh (HDIM + 4)
#define PW   (BKC / 2)
#define PSTRh (PW + 4)

__device__ __forceinline__ unsigned f2h2(float x, float y) {
    __half2 h = __floats2half2_rn(x, y);
    return *reinterpret_cast<unsigned*>(&h);
}

__global__ void __launch_bounds__(256)
flash_attn_kernel(const __half* __restrict__ QKV, __half* __restrict__ O)
{
    extern __shared__ unsigned fa_sm[];
    unsigned* sQ = fa_sm;
    unsigned* sK = sQ + BQ  * QSTRh;
    unsigned* sV = sK + BKC * QSTRh;
    unsigned* sP = sV + PW  * VSTRh;

    int z  = blockIdx.z;
    int b  = z / HEADS, h = z % HEADS;
    int q0 = blockIdx.y * BQ;

    const __half* Qg = QKV + (long long)b * SEQ * (3 * DIM) + h * HDIM;
    const __half* Kg = Qg + DIM;
    const __half* Vg = Qg + 2 * DIM;

    int tid  = threadIdx.x;
    int wid  = tid >> 5, lane = tid & 31;
    int qr   = lane >> 2, r = lane & 3;
    int mrow = wid * 16;

    unsigned sQb = (unsigned)__cvta_generic_to_shared(sQ);
    unsigned sKb = (unsigned)__cvta_generic_to_shared(sK);
    unsigned sPb = (unsigned)__cvta_generic_to_shared(sP);
    unsigned qoff = (((lane & 15) * QSTRh + (lane >> 4) * 4) << 2);
    unsigned koff = (((lane & 7)  * QSTRh + ((lane >> 3) & 1) * 4) << 2);
    unsigned poff = (((lane & 15) * PSTRh + (lane >> 4) * 4) << 2);

    #pragma unroll
    for (int it = 0; it < BQ * HDIM / (256 * 8); it++) {
        int idx = (tid + it * 256) * 8;
        int m = idx / HDIM, d = idx % HDIM;
        uint4 v = make_uint4(0u, 0u, 0u, 0u);
        if (q0 + m < SEQ)
            v = *(const uint4*)(Qg + (long long)(q0 + m) * (3 * DIM) + d);
        *(uint4*)&sQ[m * QSTRh + (d >> 1)] = v;
    }

    float acc_O[8][4];
    #pragma unroll
    for (int j = 0; j < 8; j++)
        #pragma unroll
        for (int t = 0; t < 4; t++) acc_O[j][t] = 0.f;
    float mstate[2] = { -3.0e38f, -3.0e38f };
    float lstate[2] = { 0.f, 0.f };

    const int nchunks = (SEQ + BKC - 1) / BKC;
    for (int c = 0; c < nchunks; c++) {
        int kb = c * BKC;
        __syncthreads();

        #pragma unroll
        for (int it = 0; it < BKC * HDIM / (256 * 8); it++) {
            int idx = (tid + it * 256) * 8;
            int n = idx / HDIM, d = idx % HDIM;
            uint4 v = make_uint4(0u, 0u, 0u, 0u);
            if (kb + n < SEQ)
                v = *(const uint4*)(Kg + (long long)(kb + n) * (3 * DIM) + d);
            *(uint4*)&sK[n * QSTRh + (d >> 1)] = v;
        }
        {
            __half* Vh = (__half*)sV;
            #pragma unroll
            for (int it = 0; it < BKC * HDIM / (256 * 8); it++) {
                int idx = (tid + it * 256) * 8;
                int n = idx / HDIM, d = idx % HDIM;
                uint4 v = make_uint4(0u, 0u, 0u, 0u);
                if (kb + n < SEQ)
                    v = *(const uint4*)(Vg + (long long)(kb + n) * (3 * DIM) + d);
                const __half* hv = (const __half*)&v;
                int w = n >> 1, par = n & 1;
                int base = w * VSTRh + d;
                #pragma unroll
                for (int i = 0; i < 8; i++)
                    Vh[((base + i) << 1) | par] = hv[i];
            }
        }
        __syncthreads();

        float acc_S[8][4];
        #pragma unroll
        for (int j = 0; j < 8; j++)
            #pragma unroll
            for (int t = 0; t < 4; t++) acc_S[j][t] = 0.f;

        #pragma unroll
        for (int kw = 0; kw < DW; kw += 8) {
            unsigned a[4];
            ldsm_x4(a[0], a[1], a[2], a[3],
                    sQb + ((mrow * QSTRh + kw) << 2) + qoff);
            #pragma unroll
            for (int j = 0; j < 8; j++) {
                unsigned bb[2];
                asm volatile("ldmatrix.sync.aligned.m8n8.x2.shared.b16 {%0,%1}, [%2];"
                             : "=r"(bb[0]), "=r"(bb[1])
                             : "r"(sKb + (((j * 8) * QSTRh + kw) << 2) + koff));
                MMA_F16(acc_S[j], a, bb);
            }
        }

        float cmax[2] = { -3.0e38f, -3.0e38f };
        #pragma unroll
        for (int j = 0; j < 8; j++)
            #pragma unroll
            for (int t = 0; t < 4; t++) {
                int col = j * 8 + r * 2 + (t & 1);
                if (kb + col >= SEQ) acc_S[j][t] = -3.0e38f;
                cmax[t >> 1] = fmaxf(cmax[t >> 1], acc_S[j][t]);
            }
        #pragma unroll
        for (int o = 1; o <= 2; o <<= 1) {
            cmax[0] = fmaxf(cmax[0], __shfl_xor_sync(0xffffffffu, cmax[0], o));
            cmax[1] = fmaxf(cmax[1], __shfl_xor_sync(0xffffffffu, cmax[1], o));
        }
        float mnew[2]  = { fmaxf(mstate[0], cmax[0]), fmaxf(mstate[1], cmax[1]) };
        float scale[2] = { __expf(mstate[0] - mnew[0]), __expf(mstate[1] - mnew[1]) };
        float csum[2] = { 0.f, 0.f };
        #pragma unroll
        for (int j = 0; j < 8; j++)
            #pragma unroll
            for (int t = 0; t < 4; t++) {
                float p = __expf(acc_S[j][t] - mnew[t >> 1]);
                acc_S[j][t] = p;
                csum[t >> 1] += p;
            }
        #pragma unroll
        for (int o = 1; o <= 2; o <<= 1) {
            csum[0] += __shfl_xor_sync(0xffffffffu, csum[0], o);
            csum[1] += __shfl_xor_sync(0xffffffffu, csum[1], o);
        }
        lstate[0] = lstate[0] * scale[0] + csum[0];
        lstate[1] = lstate[1] * scale[1] + csum[1];
        mstate[0] = mnew[0];
        mstate[1] = mnew[1];
        #pragma unroll
        for (int j = 0; j < 8; j++)
            #pragma unroll
            for (int t = 0; t < 4; t++)
                acc_O[j][t] *= scale[t >> 1];

        #pragma unroll
        for (int j = 0; j < 8; j++) {
            sP[(mrow + qr    ) * PSTRh + j * 4 + r] = f2h2(acc_S[j][0], acc_S[j][1]);
            sP[(mrow + qr + 8) * PSTRh + j * 4 + r] = f2h2(acc_S[j][2], acc_S[j][3]);
        }
        __syncwarp();

        #pragma unroll
        for (int kw = 0; kw < PW; kw += 8) {
            unsigned a[4];
            ldsm_x4(a[0], a[1], a[2], a[3],
                    sPb + ((mrow * PSTRh + kw) << 2) + poff);
            #pragma unroll
            for (int j = 0; j < 8; j++) {
                unsigned bb[2] = { sV[(kw + r    ) * VSTRh + j * 8 + qr],
                                   sV[(kw + r + 4) * VSTRh + j * 8 + qr] };
                MMA_F16(acc_O[j], a, bb);
            }
        }
    }

    float inv[2] = { 1.f / lstate[0], 1.f / lstate[1] };
    #pragma unroll
    for (int j = 0; j < 8; j++)
        #pragma unroll
        for (int t = 0; t < 4; t++) {
            int row = q0 + mrow + qr + ((t >= 2) ? 8 : 0);
            int col = j * 8 + r * 2 + (t & 1);
            if (row < SEQ)
                O[((long long)b * SEQ + row) * DIM + h * HDIM + col] =
                    __float2half_rn(acc_O[j][t] * inv[t >> 1]);
        }
}

// ---------------- reductions -------------------------------------------------
__device__ __forceinline__ float blockReduceSum(float v, volatile float* sh) {
    int lane = threadIdx.x & 31, w = threadIdx.x >> 5;
    #pragma unroll
    for (int o = 16; o; o >>= 1) v += __shfl_down_sync(0xffffffffu, v, o);
    if (lane == 0) sh[w] = v;
    __syncthreads();
    if (threadIdx.x < 32) {
        v = (threadIdx.x < 8) ? sh[threadIdx.x] : 0.f;
        #pragma unroll
        for (int o = 4; o; o >>= 1) v += __shfl_down_sync(0xffffffffu, v, o);
        if (lane == 0) sh[0] = v;
    }
    __syncthreads();
    return sh[0];
}

// ---------------- layernorm (fp32 in, fp16 out) -------------------------------
__global__ void __launch_bounds__(256)
layernorm_kernel(const float* __restrict__ X, const float* __restrict__ g,
                 const float* __restrict__ b, __half* __restrict__ Y)
{
    long long row = blockIdx.x;
    const float* x = X + row * DIM;
    __shared__ float sh0[8], sh1[8];
    float v0 = x[threadIdx.x], v1 = x[threadIdx.x + 256], v2 = x[threadIdx.x + 512];
    float sum  = blockReduceSum(v0 + v1 + v2, sh0);
    float sum2 = blockReduceSum(v0 * v0 + v1 * v1 + v2 * v2, sh1);
    float m   = sum * (1.f / DIM);
    float var = sum2 * (1.f / DIM) - m * m;
    float inv = rsqrtf(var + 1e-5f);
    __half* y = Y + row * DIM;
    #pragma unroll
    for (int i = 0; i < 3; i++) {
        int c = threadIdx.x + i * 256;
        float xv = (i == 0) ? v0 : (i == 1) ? v1 : v2;
        y[c] = __float2half_rn((xv - m) * inv * g[c] + b[c]);
    }
}

// ---------------- patchify (fp16 out) -----------------------------------------
__global__ void __launch_bounds__(256)
patchify_kernel(const float* __restrict__ img)
{
    int idx = blockIdx.x * 256 + threadIdx.x;
    if (idx >= BATCH * NPATCH * PDIM) return;
    int pd = idx % PDIM;
    int t  = idx / PDIM;
    int patch = t % NPATCH;
    int b     = t / NPATCH;
    int c  = pd % 3;
    int pp = pd / 3;
    int p2 = pp % PSZ, p1 = pp / PSZ;
    int wx = patch % HP, hy = patch / HP;
    g_Ph[idx] = __float2half_rn(
        img[(((long long)b * 3 + c) * IMGH + hy * PSZ + p1) * IMGH + wx * PSZ + p2]);
}

// ---------------- assemble: cls + pos add (fp32) ------------------------------
__global__ void __launch_bounds__(256)
assemble_kernel(const float* __restrict__ emb, const float* __restrict__ cls,
                const float* __restrict__ pos)
{
    int idx = blockIdx.x * 256 + threadIdx.x;
    if (idx >= BATCH * SEQ * DIM) return;
    int d = idx % DIM;
    int t = idx / DIM;
    int s = t % SEQ;
    int b = t / SEQ;
    float v;
    if (s == 0) v = cls[d] + pos[d];
    else        v = emb[((long long)b * NPATCH + (s - 1)) * DIM + d] + pos[(long long)s * DIM + d];
    g_X[idx] = v;
}

// ---------------- output: drop cls token --------------------------------------
__global__ void __launch_bounds__(256)
output_kernel(float* __restrict__ out)
{
    int idx = blockIdx.x * 256 + threadIdx.x;
    if (idx >= BATCH * NPATCH * DIM) return;
    int d = idx % DIM;
    int t = idx / DIM;
    int s = t % NPATCH;
    int b = t / NPATCH;
    out[idx] = g_X[((long long)b * SEQ + (s + 1)) * DIM + d];
}

// ---------------- host driver -------------------------------------------------
extern "C" void kernel_launch(void* const* d_in, const int* in_sizes, int n_in,
                              void* d_out, int out_size)
{
    const float* img   = (const float*)d_in[0];
    const float* pos   = (const float*)d_in[1];
    const float* cls   = (const float*)d_in[2];
    const float* pw    = (const float*)d_in[3];
    const float* pb    = (const float*)d_in[4];
    const float* ln1g  = (const float*)d_in[5];
    const float* ln1b  = (const float*)d_in[6];
    const float* qkvw  = (const float*)d_in[7];
    const float* outw  = (const float*)d_in[8];
    const float* outb  = (const float*)d_in[9];
    const float* ln2g  = (const float*)d_in[10];
    const float* ln2b  = (const float*)d_in[11];
    const float* ff1w  = (const float*)d_in[12];
    const float* ff1b  = (const float*)d_in[13];
    const float* ff2w  = (const float*)d_in[14];
    const float* ff2b  = (const float*)d_in[15];
    float* out = (float*)d_out;

    float  *pX, *pYf;
    __half *pYh, *pQKV, *pO, *pH, *pP, *pWw;
    cudaGetSymbolAddress((void**)&pX,   g_X);
    cudaGetSymbolAddress((void**)&pYf,  g_Yf);
    cudaGetSymbolAddress((void**)&pYh,  g_Yh);
    cudaGetSymbolAddress((void**)&pQKV, g_QKVh);
    cudaGetSymbolAddress((void**)&pO,   g_Oh);
    cudaGetSymbolAddress((void**)&pH,   g_Hh);
    cudaGetSymbolAddress((void**)&pP,   g_Ph);
    cudaGetSymbolAddress((void**)&pWw,  g_W16);

    const int Mfull = BATCH * SEQ;
    const int Mpat  = BATCH * NPATCH;

    const int FA_SMEM = (BQ * QSTRh + BKC * QSTRh + PW * VSTRh + BQ * PSTRh) * 4;
    cudaFuncSetAttribute((const void*)flash_attn_kernel,
                         cudaFuncAttributeMaxDynamicSharedMemorySize, FA_SMEM);

    auto grid = [](int M, int N, int Z) {
        return dim3((N + 127) / 128, (M + 127) / 128, Z);
    };
    auto cgrid = [](int n) { int g = (n + 255) / 256; return g > 4096 ? 4096 : g; };

    // 0) convert weights to fp16
    f2h_kernel<<<cgrid(SZ_PW),  256>>>(pw,   pWw + OFF_PW,  SZ_PW);
    f2h_kernel<<<cgrid(SZ_QKV), 256>>>(qkvw, pWw + OFF_QKV, SZ_QKV);
    f2h_kernel<<<cgrid(SZ_OUT), 256>>>(outw, pWw + OFF_OUT, SZ_OUT);
    f2h_kernel<<<cgrid(SZ_FF1), 256>>>(ff1w, pWw + OFF_FF1, SZ_FF1);
    f2h_kernel<<<cgrid(SZ_FF2), 256>>>(ff2w, pWw + OFF_FF2, SZ_FF2);

    // 1) patchify + patch embed + assemble
    patchify_kernel<<<(BATCH * NPATCH * PDIM + 255) / 256, 256>>>(img);
    gemm_tc<128,128,32,2,4><<<grid(Mpat, DIM, 1), 256>>>(
        pP, PDIM,  pWw + OFF_PW, DIM,  pb,
        pYf, nullptr, DIM,  Mpat, DIM, PDIM, 0);
    assemble_kernel<<<(BATCH * SEQ * DIM + 255) / 256, 256>>>(pYf, cls, pos);

    // 2) transformer layers
    for (int l = 0; l < DEPTH; l++) {
        const __half* wqkv = pWw + OFF_QKV + (long long)l * DIM * 3 * DIM;
        const __half* wo   = pWw + OFF_OUT + (long long)l * DIM * DIM;
        const __half* w1   = pWw + OFF_FF1 + (long long)l * DIM * MLPD;
        const __half* w2   = pWw + OFF_FF2 + (long long)l * MLPD * DIM;
        const float* bo = outb + (long long)l * DIM;
        const float* b1 = ff1b + (long long)l * MLPD;
        const float* b2 = ff2b + (long long)l * DIM;

        layernorm_kernel<<<Mfull, 256>>>(pX, ln1g + (long long)l * DIM,
                                         ln1b + (long long)l * DIM, pYh);
        gemm_tc<128,128,32,2,4><<<grid(Mfull, 3 * DIM, 1), 256>>>(
            pYh, DIM,  wqkv, 3 * DIM,  nullptr,
            nullptr, pQKV, 3 * DIM,  Mfull, 3 * DIM, DIM, 0);
        {
            dim3 g(1, (SEQ + BQ - 1) / BQ, BATCH * HEADS);
            flash_attn_kernel<<<g, 256, FA_SMEM>>>(pQKV, pO);
        }
        gemm_tc<128,128,32,2,4><<<grid(Mfull, DIM, 1), 256>>>(
            pO, DIM,  wo, DIM,  bo,
            pX, nullptr, DIM,  Mfull, DIM, DIM, 2);
        layernorm_kernel<<<Mfull, 256>>>(pX, ln2g + (long long)l * DIM,
                                         ln2b + (long long)l * DIM, pYh);
        gemm_tc<128,128,32,2,4><<<grid(Mfull, MLPD, 1), 256>>>(
            pYh, DIM,  w1, MLPD,  b1,
            nullptr, pH, MLPD,  Mfull, MLPD, DIM, 1);
        gemm_tc<128,128,32,2,4><<<grid(Mfull, DIM, 1), 256>>>(
            pH, MLPD,  w2, DIM,  b2,
            pX, nullptr, DIM,  Mfull, DIM, MLPD, 2);
    }

    // 3) drop cls token -> output
    output_kernel<<<(BATCH * NPATCH * DIM + 255) / 256, 256>>>(out);
}

// round 15
// speedup vs baseline: 2.3505x; 1.0878x over previous
#include <cuda_runtime.h>
#include <cuda_fp16.h>
#include <math.h>
#include <stdint.h>

#define BATCH  8
#define SEQ    577
#define DIM    768
#define HEADS  12
#define HDIM   64
#define MLPD   3072
#define DEPTH  8
#define NPATCH 576
#define PDIM   768
#define IMGH   384
#define PSZ    16
#define HP     24

// fp16 weight buffer offsets (in halfs)
#define OFF_PW   0
#define SZ_PW    (PDIM * DIM)
#define OFF_QKV  (OFF_PW + SZ_PW)
#define SZ_QKV   (DEPTH * DIM * 3 * DIM)
#define OFF_OUT  (OFF_QKV + SZ_QKV)
#define SZ_OUT   (DEPTH * DIM * DIM)
#define OFF_FF1  (OFF_OUT + SZ_OUT)
#define SZ_FF1   (DEPTH * DIM * MLPD)
#define OFF_FF2  (OFF_FF1 + SZ_FF1)
#define SZ_FF2   (DEPTH * MLPD * DIM)
#define W16_TOTAL (OFF_FF2 + SZ_FF2)

// ---------------- scratch (device globals; allocation is banned) ------------
__device__ float  g_X   [BATCH * SEQ * DIM];
__device__ float  g_Yf  [BATCH * SEQ * DIM];
__device__ __half g_Yh  [BATCH * SEQ * DIM];
__device__ __half g_QKVh[BATCH * SEQ * 3 * DIM];
__device__ __half g_Oh  [BATCH * SEQ * DIM];
__device__ __half g_Hh  [BATCH * SEQ * MLPD];
__device__ __half g_Ph  [BATCH * NPATCH * PDIM];
__device__ __half g_W16 [W16_TOTAL];

// ---------------- helpers ----------------------------------------------------
#define MMA_F16(d, a, b)                                                      \
    asm volatile("mma.sync.aligned.m16n8k16.row.col.f32.f16.f16.f32 "         \
                 "{%0,%1,%2,%3}, {%4,%5,%6,%7}, {%8,%9}, {%0,%1,%2,%3};\n"    \
                 : "+f"(d[0]), "+f"(d[1]), "+f"(d[2]), "+f"(d[3])             \
                 : "r"(a[0]), "r"(a[1]), "r"(a[2]), "r"(a[3]),                \
                   "r"(b[0]), "r"(b[1]))

__device__ __forceinline__ void ldsm_x4(unsigned& d0, unsigned& d1,
                                        unsigned& d2, unsigned& d3,
                                        unsigned addr) {
    asm volatile("ldmatrix.sync.aligned.m8n8.x4.shared.b16 {%0,%1,%2,%3}, [%4];"
                 : "=r"(d0), "=r"(d1), "=r"(d2), "=r"(d3) : "r"(addr));
}
__device__ __forceinline__ void ldsm_x4t(unsigned& d0, unsigned& d1,
                                         unsigned& d2, unsigned& d3,
                                         unsigned addr) {
    asm volatile("ldmatrix.sync.aligned.m8n8.x4.trans.shared.b16 {%0,%1,%2,%3}, [%4];"
                 : "=r"(d0), "=r"(d1), "=r"(d2), "=r"(d3) : "r"(addr));
}
__device__ __forceinline__ void ldsm_x2t(unsigned& d0, unsigned& d1,
                                         unsigned addr) {
    asm volatile("ldmatrix.sync.aligned.m8n8.x2.trans.shared.b16 {%0,%1}, [%2];"
                 : "=r"(d0), "=r"(d1) : "r"(addr));
}
__device__ __forceinline__ void ldsm_x2(unsigned& d0, unsigned& d1,
                                        unsigned addr) {
    asm volatile("ldmatrix.sync.aligned.m8n8.x2.shared.b16 {%0,%1}, [%2];"
                 : "=r"(d0), "=r"(d1) : "r"(addr));
}

__device__ __forceinline__ void cpa16(unsigned saddr, const void* gptr, bool pred) {
    int sz = pred ? 16 : 0;
    asm volatile("cp.async.cg.shared.global [%0], [%1], 16, %2;\n"
                 :: "r"(saddr), "l"(gptr), "r"(sz));
}
#define CP_COMMIT() asm volatile("cp.async.commit_group;\n" ::: "memory")
#define CP_WAIT(n)  asm volatile("cp.async.wait_group %0;\n" :: "n"(n) : "memory")

// ---------------- weight fp32 -> fp16 conversion (vectorized) -----------------
__global__ void __launch_bounds__(256)
f2h_kernel(const float* __restrict__ s, __half* __restrict__ d, int n)
{
    int i = (blockIdx.x * 256 + threadIdx.x) * 8;
    int stride = gridDim.x * 256 * 8;
    for (; i < n; i += stride) {
        float4 a = *(const float4*)(s + i);
        float4 b = *(const float4*)(s + i + 4);
        __half2 h[4] = { __floats2half2_rn(a.x, a.y), __floats2half2_rn(a.z, a.w),
                         __floats2half2_rn(b.x, b.y), __floats2half2_rn(b.z, b.w) };
        *(uint2*)(d + i)     = *(uint2*)&h[0];
        *(uint2*)(d + i + 4) = *(uint2*)&h[2];
    }
}

// ---------------- fp16 tensor-core GEMM: cp.async + ldmatrix, BK=64 ----------
// C = op( A @ B (+ bias) ). A half [M,K] row-major (row-pred), B half [K,N].
// Output: Ch!=null -> fp16; else fp32 (fuse==2 residual add).
// Invariants: K%BK==0, N%BN==0, 16B-aligned rows. Dynamic smem.
template<int BM, int BN, int BK, int WM, int WN>
__global__ void __launch_bounds__(WM * WN * 32)
gemm_tc(const __half* __restrict__ A, int lda,
        const __half* __restrict__ Bm, int ldb,
        const float* __restrict__ bias,
        float* __restrict__ C, __half* __restrict__ Ch, int ldc,
        int M, int N, int K, int fuse)
{
    constexpr int NTHREADS = WM * WN * 32;
    constexpr int MT = (BM / WM) / 16;
    constexpr int NT = (BN / WN) / 8;
    constexpr int A_IT = BM * BK / (NTHREADS * 8);
    constexpr int B_IT = BK * BN / (NTHREADS * 8);
    constexpr int AW   = BK / 2;          // A k-words per tile
    constexpr int ASTR = AW + 4;          // 36 words (BK=64): conflict-free
    constexpr int BSTR = BN / 2 + 4;      // 68 words: conflict-free trans-ldsm
    constexpr int ASZ = BM * ASTR;
    constexpr int BSZ = BK * BSTR;

    extern __shared__ unsigned gsm[];
    unsigned* As = gsm;                   // 2 x ASZ
    unsigned* Bs = gsm + 2 * ASZ;         // 2 x BSZ

    int r0 = blockIdx.y * BM;
    int c0 = blockIdx.x * BN;
    int tid  = threadIdx.x;
    int wid  = tid >> 5, lane = tid & 31;
    int wm   = wid / WN, wn = wid % WN;
    int q    = lane >> 2, r = lane & 3;

    unsigned asBase = (unsigned)__cvta_generic_to_shared(As);
    unsigned bsBase = (unsigned)__cvta_generic_to_shared(Bs);
    unsigned aoff = (((lane & 15) * ASTR + (lane >> 4) * 4) << 2);
    int mi = lane >> 3;
    unsigned boff = ((((lane & 7) + (mi & 1) * 8) * BSTR + (mi >> 1) * 4) << 2);

    float acc[MT][NT][4];
    #pragma unroll
    for (int i = 0; i < MT; i++)
        #pragma unroll
        for (int j = 0; j < NT; j++)
            #pragma unroll
            for (int t = 0; t < 4; t++) acc[i][j][t] = 0.f;

    auto loadTile = [&](int k0, int buf) {
        #pragma unroll
        for (int it = 0; it < A_IT; it++) {
            int idx = (tid + it * NTHREADS) * 8;
            int m = idx / BK, kk = idx % BK;
            bool p = (r0 + m) < M;
            int row = p ? (r0 + m) : 0;
            cpa16(asBase + ((buf * ASZ + m * ASTR + (kk >> 1)) << 2),
                  A + (long long)row * lda + k0 + kk, p);
        }
        #pragma unroll
        for (int it = 0; it < B_IT; it++) {
            int idx = (tid + it * NTHREADS) * 8;
            int kk = idx / BN, n = idx % BN;
            cpa16(bsBase + ((buf * BSZ + kk * BSTR + (n >> 1)) << 2),
                  Bm + (long long)(k0 + kk) * ldb + c0 + n, true);
        }
        CP_COMMIT();
    };

    int T = K / BK;
    loadTile(0, 0);

    for (int t = 0; t < T; t++) {
        if (t + 1 < T) {
            loadTile((t + 1) * BK, (t + 1) & 1);
            CP_WAIT(1);
        } else {
            CP_WAIT(0);
        }
        __syncthreads();

        unsigned aB = asBase + ((t & 1) * ASZ << 2);
        unsigned bB = bsBase + ((t & 1) * BSZ << 2);
        int nb_w = wn * (BN / WN) / 2;

        #pragma unroll
        for (int kw = 0; kw < AW; kw += 8) {
            unsigned af[MT][4];
            unsigned bf[NT][2];
            #pragma unroll
            for (int i = 0; i < MT; i++) {
                int m = wm * (BM / WM) + i * 16;
                ldsm_x4(af[i][0], af[i][1], af[i][2], af[i][3],
                        aB + ((m * ASTR + kw) << 2) + aoff);
            }
            int kk = kw * 2;
            #pragma unroll
            for (int jj = 0; jj < NT / 2; jj++) {
                ldsm_x4t(bf[2 * jj][0], bf[2 * jj][1],
                         bf[2 * jj + 1][0], bf[2 * jj + 1][1],
                         bB + ((kk * BSTR + nb_w + jj * 8) << 2) + boff);
            }
            #pragma unroll
            for (int i = 0; i < MT; i++)
                #pragma unroll
                for (int j = 0; j < NT; j++)
                    MMA_F16(acc[i][j], af[i], bf[j]);
        }
        __syncthreads();
    }

    // ---- epilogue ----
    #pragma unroll
    for (int i = 0; i < MT; i++) {
        #pragma unroll
        for (int j = 0; j < NT; j++) {
            #pragma unroll
            for (int t = 0; t < 4; t++) {
                int row = r0 + wm * (BM / WM) + i * 16 + q + ((t >= 2) ? 8 : 0);
                int col = c0 + wn * (BN / WN) + j * 8 + r * 2 + (t & 1);
                if (row >= M) continue;
                float v = acc[i][j][t];
                if (bias) v += bias[col];
                if (fuse == 1) v = 0.5f * v * (1.f + erff(v * 0.70710678118654752f));
                long long off = (long long)row * ldc + col;
                if (Ch) {
                    Ch[off] = __float2half_rn(v);
                } else {
                    if (fuse == 2) v += C[off];
                    C[off] = v;
                }
            }
        }
    }
}

// ---------------- fused flash attention (natural V + trans ldsm) --------------
#define BQ   128
#define BKC  64
#define DW   (HDIM / 2)
#define QSTRh (DW + 4)        // 36 words
#define PW   (BKC / 2)
#define PSTRh (PW + 4)        // 36 words

__device__ __forceinline__ unsigned f2h2(float x, float y) {
    __half2 h = __floats2half2_rn(x, y);
    return *reinterpret_cast<unsigned*>(&h);
}

__global__ void __launch_bounds__(256)
flash_attn_kernel(const __half* __restrict__ QKV, __half* __restrict__ O)
{
    extern __shared__ unsigned fa_sm[];
    unsigned* sQ = fa_sm;                  // [BQ ][QSTRh]
    unsigned* sK = sQ + BQ  * QSTRh;       // [BKC][QSTRh]
    unsigned* sV = sK + BKC * QSTRh;       // [BKC][QSTRh] natural [key][d]
    unsigned* sP = sV + BKC * QSTRh;       // [BQ ][PSTRh] packed key-pairs

    int z  = blockIdx.z;
    int b  = z / HEADS, h = z % HEADS;
    int q0 = blockIdx.y * BQ;

    const __half* Qg = QKV + (long long)b * SEQ * (3 * DIM) + h * HDIM;
    const __half* Kg = Qg + DIM;
    const __half* Vg = Qg + 2 * DIM;

    int tid  = threadIdx.x;
    int wid  = tid >> 5, lane = tid & 31;
    int qr   = lane >> 2, r = lane & 3;
    int mrow = wid * 16;

    unsigned sQb = (unsigned)__cvta_generic_to_shared(sQ);
    unsigned sKb = (unsigned)__cvta_generic_to_shared(sK);
    unsigned sVb = (unsigned)__cvta_generic_to_shared(sV);
    unsigned sPb = (unsigned)__cvta_generic_to_shared(sP);
    unsigned qoff = (((lane & 15) * QSTRh + (lane >> 4) * 4) << 2);
    unsigned koff = (((lane & 7)  * QSTRh + ((lane >> 3) & 1) * 4) << 2);
    unsigned poff = (((lane & 15) * PSTRh + (lane >> 4) * 4) << 2);
    unsigned voff = ((((lane & 7) + ((lane >> 3) & 1) * 8) * QSTRh) << 2);

    #pragma unroll
    for (int it = 0; it < BQ * HDIM / (256 * 8); it++) {
        int idx = (tid + it * 256) * 8;
        int m = idx / HDIM, d = idx % HDIM;
        uint4 v = make_uint4(0u, 0u, 0u, 0u);
        if (q0 + m < SEQ)
            v = *(const uint4*)(Qg + (long long)(q0 + m) * (3 * DIM) + d);
        *(uint4*)&sQ[m * QSTRh + (d >> 1)] = v;
    }

    float acc_O[8][4];
    #pragma unroll
    for (int j = 0; j < 8; j++)
        #pragma unroll
        for (int t = 0; t < 4; t++) acc_O[j][t] = 0.f;
    float mstate[2] = { -3.0e38f, -3.0e38f };
    float lstate[2] = { 0.f, 0.f };

    const int nchunks = (SEQ + BKC - 1) / BKC;
    for (int c = 0; c < nchunks; c++) {
        int kb = c * BKC;
        __syncthreads();

        #pragma unroll
        for (int it = 0; it < BKC * HDIM / (256 * 8); it++) {
            int idx = (tid + it * 256) * 8;
            int n = idx / HDIM, d = idx % HDIM;
            uint4 v = make_uint4(0u, 0u, 0u, 0u);
            if (kb + n < SEQ)
                v = *(const uint4*)(Kg + (long long)(kb + n) * (3 * DIM) + d);
            *(uint4*)&sK[n * QSTRh + (d >> 1)] = v;
        }
        #pragma unroll
        for (int it = 0; it < BKC * HDIM / (256 * 8); it++) {
            int idx = (tid + it * 256) * 8;
            int n = idx / HDIM, d = idx % HDIM;
            uint4 v = make_uint4(0u, 0u, 0u, 0u);
            if (kb + n < SEQ)
                v = *(const uint4*)(Vg + (long long)(kb + n) * (3 * DIM) + d);
            *(uint4*)&sV[n * QSTRh + (d >> 1)] = v;
        }
        __syncthreads();

        // ---- S = Q @ K^T ----
        float acc_S[8][4];
        #pragma unroll
        for (int j = 0; j < 8; j++)
            #pragma unroll
            for (int t = 0; t < 4; t++) acc_S[j][t] = 0.f;

        #pragma unroll
        for (int kw = 0; kw < DW; kw += 8) {
            unsigned a[4];
            ldsm_x4(a[0], a[1], a[2], a[3],
                    sQb + ((mrow * QSTRh + kw) << 2) + qoff);
            #pragma unroll
            for (int j = 0; j < 8; j++) {
                unsigned bb[2];
                ldsm_x2(bb[0], bb[1],
                        sKb + (((j * 8) * QSTRh + kw) << 2) + koff);
                MMA_F16(acc_S[j], a, bb);
            }
        }

        // ---- mask, online softmax ----
        float cmax[2] = { -3.0e38f, -3.0e38f };
        #pragma unroll
        for (int j = 0; j < 8; j++)
            #pragma unroll
            for (int t = 0; t < 4; t++) {
                int col = j * 8 + r * 2 + (t & 1);
                if (kb + col >= SEQ) acc_S[j][t] = -3.0e38f;
                cmax[t >> 1] = fmaxf(cmax[t >> 1], acc_S[j][t]);
            }
        #pragma unroll
        for (int o = 1; o <= 2; o <<= 1) {
            cmax[0] = fmaxf(cmax[0], __shfl_xor_sync(0xffffffffu, cmax[0], o));
            cmax[1] = fmaxf(cmax[1], __shfl_xor_sync(0xffffffffu, cmax[1], o));
        }
        float mnew[2]  = { fmaxf(mstate[0], cmax[0]), fmaxf(mstate[1], cmax[1]) };
        float scale[2] = { __expf(mstate[0] - mnew[0]), __expf(mstate[1] - mnew[1]) };
        float csum[2] = { 0.f, 0.f };
        #pragma unroll
        for (int j = 0; j < 8; j++)
            #pragma unroll
            for (int t = 0; t < 4; t++) {
                float p = __expf(acc_S[j][t] - mnew[t >> 1]);
                acc_S[j][t] = p;
                csum[t >> 1] += p;
            }
        #pragma unroll
        for (int o = 1; o <= 2; o <<= 1) {
            csum[0] += __shfl_xor_sync(0xffffffffu, csum[0], o);
            csum[1] += __shfl_xor_sync(0xffffffffu, csum[1], o);
        }
        lstate[0] = lstate[0] * scale[0] + csum[0];
        lstate[1] = lstate[1] * scale[1] + csum[1];
        mstate[0] = mnew[0];
        mstate[1] = mnew[1];
        #pragma unroll
        for (int j = 0; j < 8; j++)
            #pragma unroll
            for (int t = 0; t < 4; t++)
                acc_O[j][t] *= scale[t >> 1];

        // ---- P -> smem packed key-pairs ----
        #pragma unroll
        for (int j = 0; j < 8; j++) {
            sP[(mrow + qr    ) * PSTRh + j * 4 + r] = f2h2(acc_S[j][0], acc_S[j][1]);
            sP[(mrow + qr + 8) * PSTRh + j * 4 + r] = f2h2(acc_S[j][2], acc_S[j][3]);
        }
        __syncwarp();

        // ---- O += P @ V (V natural layout, trans-ldsm B fragments) ----
        #pragma unroll
        for (int kw = 0; kw < PW; kw += 8) {
            unsigned a[4];
            ldsm_x4(a[0], a[1], a[2], a[3],
                    sPb + ((mrow * PSTRh + kw) << 2) + poff);
            #pragma unroll
            for (int j = 0; j < 8; j++) {
                unsigned bb[2];
                ldsm_x2t(bb[0], bb[1],
                         sVb + (((kw * 2) * QSTRh + j * 4) << 2) + voff);
                MMA_F16(acc_O[j], a, bb);
            }
        }
    }

    float inv[2] = { 1.f / lstate[0], 1.f / lstate[1] };
    #pragma unroll
    for (int j = 0; j < 8; j++)
        #pragma unroll
        for (int t = 0; t < 4; t++) {
            int row = q0 + mrow + qr + ((t >= 2) ? 8 : 0);
            int col = j * 8 + r * 2 + (t & 1);
            if (row < SEQ)
                O[((long long)b * SEQ + row) * DIM + h * HDIM + col] =
                    __float2half_rn(acc_O[j][t] * inv[t >> 1]);
        }
}

// ---------------- reductions -------------------------------------------------
__device__ __forceinline__ float blockReduceSum(float v, volatile float* sh) {
    int lane = threadIdx.x & 31, w = threadIdx.x >> 5;
    #pragma unroll
    for (int o = 16; o; o >>= 1) v += __shfl_down_sync(0xffffffffu, v, o);
    if (lane == 0) sh[w] = v;
    __syncthreads();
    if (threadIdx.x < 32) {
        v = (threadIdx.x < 8) ? sh[threadIdx.x] : 0.f;
        #pragma unroll
        for (int o = 4; o; o >>= 1) v += __shfl_down_sync(0xffffffffu, v, o);
        if (lane == 0) sh[0] = v;
    }
    __syncthreads();
    return sh[0];
}

// ---------------- layernorm (fp32 in, fp16 out) -------------------------------
__global__ void __launch_bounds__(256)
layernorm_kernel(const float* __restrict__ X, const float* __restrict__ g,
                 const float* __restrict__ b, __half* __restrict__ Y)
{
    long long row = blockIdx.x;
    const float* x = X + row * DIM;
    __shared__ float sh0[8], sh1[8];
    float v0 = x[threadIdx.x], v1 = x[threadIdx.x + 256], v2 = x[threadIdx.x + 512];
    float sum  = blockReduceSum(v0 + v1 + v2, sh0);
    float sum2 = blockReduceSum(v0 * v0 + v1 * v1 + v2 * v2, sh1);
    float m   = sum * (1.f / DIM);
    float var = sum2 * (1.f / DIM) - m * m;
    float inv = rsqrtf(var + 1e-5f);
    __half* y = Y + row * DIM;
    #pragma unroll
    for (int i = 0; i < 3; i++) {
        int c = threadIdx.x + i * 256;
        float xv = (i == 0) ? v0 : (i == 1) ? v1 : v2;
        y[c] = __float2half_rn((xv - m) * inv * g[c] + b[c]);
    }
}

// ---------------- patchify (fp16 out) -----------------------------------------
__global__ void __launch_bounds__(256)
patchify_kernel(const float* __restrict__ img)
{
    int idx = blockIdx.x * 256 + threadIdx.x;
    if (idx >= BATCH * NPATCH * PDIM) return;
    int pd = idx % PDIM;
    int t  = idx / PDIM;
    int patch = t % NPATCH;
    int b     = t / NPATCH;
    int c  = pd % 3;
    int pp = pd / 3;
    int p2 = pp % PSZ, p1 = pp / PSZ;
    int wx = patch % HP, hy = patch / HP;
    g_Ph[idx] = __float2half_rn(
        img[(((long long)b * 3 + c) * IMGH + hy * PSZ + p1) * IMGH + wx * PSZ + p2]);
}

// ---------------- assemble: cls + pos add (fp32) ------------------------------
__global__ void __launch_bounds__(256)
assemble_kernel(const float* __restrict__ emb, const float* __restrict__ cls,
                const float* __restrict__ pos)
{
    int idx = blockIdx.x * 256 + threadIdx.x;
    if (idx >= BATCH * SEQ * DIM) return;
    int d = idx % DIM;
    int t = idx / DIM;
    int s = t % SEQ;
    int b = t / SEQ;
    float v;
    if (s == 0) v = cls[d] + pos[d];
    else        v = emb[((long long)b * NPATCH + (s - 1)) * DIM + d] + pos[(long long)s * DIM + d];
    g_X[idx] = v;
}

// ---------------- output: drop cls token --------------------------------------
__global__ void __launch_bounds__(256)
output_kernel(float* __restrict__ out)
{
    int idx = blockIdx.x * 256 + threadIdx.x;
    if (idx >= BATCH * NPATCH * DIM) return;
    int d = idx % DIM;
    int t = idx / DIM;
    int s = t % NPATCH;
    int b = t / NPATCH;
    out[idx] = g_X[((long long)b * SEQ + (s + 1)) * DIM + d];
}

// ---------------- host driver -------------------------------------------------
extern "C" void kernel_launch(void* const* d_in, const int* in_sizes, int n_in,
                              void* d_out, int out_size)
{
    const float* img   = (const float*)d_in[0];
    const float* pos   = (const float*)d_in[1];
    const float* cls   = (const float*)d_in[2];
    const float* pw    = (const float*)d_in[3];
    const float* pb    = (const float*)d_in[4];
    const float* ln1g  = (const float*)d_in[5];
    const float* ln1b  = (const float*)d_in[6];
    const float* qkvw  = (const float*)d_in[7];
    const float* outw  = (const float*)d_in[8];
    const float* outb  = (const float*)d_in[9];
    const float* ln2g  = (const float*)d_in[10];
    const float* ln2b  = (const float*)d_in[11];
    const float* ff1w  = (const float*)d_in[12];
    const float* ff1b  = (const float*)d_in[13];
    const float* ff2w  = (const float*)d_in[14];
    const float* ff2b  = (const float*)d_in[15];
    float* out = (float*)d_out;

    float  *pX, *pYf;
    __half *pYh, *pQKV, *pO, *pH, *pP, *pWw;
    cudaGetSymbolAddress((void**)&pX,   g_X);
    cudaGetSymbolAddress((void**)&pYf,  g_Yf);
    cudaGetSymbolAddress((void**)&pYh,  g_Yh);
    cudaGetSymbolAddress((void**)&pQKV, g_QKVh);
    cudaGetSymbolAddress((void**)&pO,   g_Oh);
    cudaGetSymbolAddress((void**)&pH,   g_Hh);
    cudaGetSymbolAddress((void**)&pP,   g_Ph);
    cudaGetSymbolAddress((void**)&pWw,  g_W16);

    const int Mfull = BATCH * SEQ;
    const int Mpat  = BATCH * NPATCH;

    // dynamic smem: 2 x (128*36 + 64*68) words = 71680 B
    const int GM_SMEM = (2 * 128 * 36 + 2 * 64 * 68) * 4;
    const int FA_SMEM = ((BQ + BKC + BKC) * QSTRh + BQ * PSTRh) * 4;  // 55296

    static int attr_done = 0;
    if (!attr_done) {
        cudaFuncSetAttribute((const void*)gemm_tc<128,128,64,2,4>,
                             cudaFuncAttributeMaxDynamicSharedMemorySize, GM_SMEM);
        cudaFuncSetAttribute((const void*)flash_attn_kernel,
                             cudaFuncAttributeMaxDynamicSharedMemorySize, FA_SMEM);
        attr_done = 1;
    }

    auto grid = [](int M, int N, int Z) {
        return dim3((N + 127) / 128, (M + 127) / 128, Z);
    };
    auto cgrid = [](int n) { int g = (n / 8 + 255) / 256; return g > 2048 ? 2048 : g; };

    // 0) convert weights to fp16
    f2h_kernel<<<cgrid(SZ_PW),  256>>>(pw,   pWw + OFF_PW,  SZ_PW);
    f2h_kernel<<<cgrid(SZ_QKV), 256>>>(qkvw, pWw + OFF_QKV, SZ_QKV);
    f2h_kernel<<<cgrid(SZ_OUT), 256>>>(outw, pWw + OFF_OUT, SZ_OUT);
    f2h_kernel<<<cgrid(SZ_FF1), 256>>>(ff1w, pWw + OFF_FF1, SZ_FF1);
    f2h_kernel<<<cgrid(SZ_FF2), 256>>>(ff2w, pWw + OFF_FF2, SZ_FF2);

    // 1) patchify + patch embed + assemble
    patchify_kernel<<<(BATCH * NPATCH * PDIM + 255) / 256, 256>>>(img);
    gemm_tc<128,128,64,2,4><<<grid(Mpat, DIM, 1), 256, GM_SMEM>>>(
        pP, PDIM,  pWw + OFF_PW, DIM,  pb,
        pYf, nullptr, DIM,  Mpat, DIM, PDIM, 0);
    assemble_kernel<<<(BATCH * SEQ * DIM + 255) / 256, 256>>>(pYf, cls, pos);

    // 2) transformer layers
    for (int l = 0; l < DEPTH; l++) {
        const __half* wqkv = pWw + OFF_QKV + (long long)l * DIM * 3 * DIM;
        const __half* wo   = pWw + OFF_OUT + (long long)l * DIM * DIM;
        const __half* w1   = pWw + OFF_FF1 + (long long)l * DIM * MLPD;
        const __half* w2   = pWw + OFF_FF2 + (long long)l * MLPD * DIM;
        const float* bo = outb + (long long)l * DIM;
        const float* b1 = ff1b + (long long)l * MLPD;
        const float* b2 = ff2b + (long long)l * DIM;

        layernorm_kernel<<<Mfull, 256>>>(pX, ln1g + (long long)l * DIM,
                                         ln1b + (long long)l * DIM, pYh);
        gemm_tc<128,128,64,2,4><<<grid(Mfull, 3 * DIM, 1), 256, GM_SMEM>>>(
            pYh, DIM,  wqkv, 3 * DIM,  nullptr,
            nullptr, pQKV, 3 * DIM,  Mfull, 3 * DIM, DIM, 0);
        {
            dim3 g(1, (SEQ + BQ - 1) / BQ, BATCH * HEADS);
            flash_attn_kernel<<<g, 256, FA_SMEM>>>(pQKV, pO);
        }
        gemm_tc<128,128,64,2,4><<<grid(Mfull, DIM, 1), 256, GM_SMEM>>>(
            pO, DIM,  wo, DIM,  bo,
            pX, nullptr, DIM,  Mfull, DIM, DIM, 2);
        layernorm_kernel<<<Mfull, 256>>>(pX, ln2g + (long long)l * DIM,
                                         ln2b + (long long)l * DIM, pYh);
        gemm_tc<128,128,64,2,4><<<grid(Mfull, MLPD, 1), 256, GM_SMEM>>>(
            pYh, DIM,  w1, MLPD,  b1,
            nullptr, pH, MLPD,  Mfull, MLPD, DIM, 1);
        gemm_tc<128,128,64,2,4><<<grid(Mfull, DIM, 1), 256, GM_SMEM>>>(
            pH, MLPD,  w2, DIM,  b2,
            pX, nullptr, DIM,  Mfull, DIM, MLPD, 2);
    }

    // 3) drop cls token -> output
    output_kernel<<<(BATCH * NPATCH * DIM + 255) / 256, 256>>>(out);
}

// round 16
// speedup vs baseline: 2.8549x; 1.2146x over previous
#include <cuda_runtime.h>
#include <cuda_fp16.h>
#include <math.h>
#include <stdint.h>

#define BATCH  8
#define SEQ    577
#define DIM    768
#define HEADS  12
#define HDIM   64
#define MLPD   3072
#define DEPTH  8
#define NPATCH 576
#define PDIM   768
#define IMGH   384
#define PSZ    16
#define HP     24

// fp16 weight buffer offsets (in halfs)
#define OFF_PW   0
#define SZ_PW    (PDIM * DIM)
#define OFF_QKV  (OFF_PW + SZ_PW)
#define SZ_QKV   (DEPTH * DIM * 3 * DIM)
#define OFF_OUT  (OFF_QKV + SZ_QKV)
#define SZ_OUT   (DEPTH * DIM * DIM)
#define OFF_FF1  (OFF_OUT + SZ_OUT)
#define SZ_FF1   (DEPTH * DIM * MLPD)
#define OFF_FF2  (OFF_FF1 + SZ_FF1)
#define SZ_FF2   (DEPTH * MLPD * DIM)
#define W16_TOTAL (OFF_FF2 + SZ_FF2)

// ---------------- scratch (device globals; allocation is banned) ------------
__device__ float  g_X   [BATCH * SEQ * DIM];
__device__ float  g_Yf  [BATCH * SEQ * DIM];
__device__ __half g_Yh  [BATCH * SEQ * DIM];
__device__ __half g_QKVh[BATCH * SEQ * 3 * DIM];
__device__ __half g_Oh  [BATCH * SEQ * DIM];
__device__ __half g_Hh  [BATCH * SEQ * MLPD];
__device__ __half g_Ph  [BATCH * NPATCH * PDIM];
__device__ __half g_W16 [W16_TOTAL];

// ---------------- helpers ----------------------------------------------------
#define MMA_F16(d, a, b)                                                      \
    asm volatile("mma.sync.aligned.m16n8k16.row.col.f32.f16.f16.f32 "         \
                 "{%0,%1,%2,%3}, {%4,%5,%6,%7}, {%8,%9}, {%0,%1,%2,%3};\n"    \
                 : "+f"(d[0]), "+f"(d[1]), "+f"(d[2]), "+f"(d[3])             \
                 : "r"(a[0]), "r"(a[1]), "r"(a[2]), "r"(a[3]),                \
                   "r"(b[0]), "r"(b[1]))

__device__ __forceinline__ void ldsm_x4(unsigned& d0, unsigned& d1,
                                        unsigned& d2, unsigned& d3,
                                        unsigned addr) {
    asm volatile("ldmatrix.sync.aligned.m8n8.x4.shared.b16 {%0,%1,%2,%3}, [%4];"
                 : "=r"(d0), "=r"(d1), "=r"(d2), "=r"(d3) : "r"(addr));
}
__device__ __forceinline__ void ldsm_x4t(unsigned& d0, unsigned& d1,
                                         unsigned& d2, unsigned& d3,
                                         unsigned addr) {
    asm volatile("ldmatrix.sync.aligned.m8n8.x4.trans.shared.b16 {%0,%1,%2,%3}, [%4];"
                 : "=r"(d0), "=r"(d1), "=r"(d2), "=r"(d3) : "r"(addr));
}
__device__ __forceinline__ void ldsm_x2t(unsigned& d0, unsigned& d1,
                                         unsigned addr) {
    asm volatile("ldmatrix.sync.aligned.m8n8.x2.trans.shared.b16 {%0,%1}, [%2];"
                 : "=r"(d0), "=r"(d1) : "r"(addr));
}
__device__ __forceinline__ void ldsm_x2(unsigned& d0, unsigned& d1,
                                        unsigned addr) {
    asm volatile("ldmatrix.sync.aligned.m8n8.x2.shared.b16 {%0,%1}, [%2];"
                 : "=r"(d0), "=r"(d1) : "r"(addr));
}

__device__ __forceinline__ void cpa16(unsigned saddr, const void* gptr, bool pred) {
    int sz = pred ? 16 : 0;
    asm volatile("cp.async.cg.shared.global [%0], [%1], 16, %2;\n"
                 :: "r"(saddr), "l"(gptr), "r"(sz));
}
#define CP_COMMIT() asm volatile("cp.async.commit_group;\n" ::: "memory")
#define CP_WAIT(n)  asm volatile("cp.async.wait_group %0;\n" :: "n"(n) : "memory")

// ---------------- weight fp32 -> fp16 conversion (vectorized) -----------------
__global__ void __launch_bounds__(256)
f2h_kernel(const float* __restrict__ s, __half* __restrict__ d, int n)
{
    int i = (blockIdx.x * 256 + threadIdx.x) * 8;
    int stride = gridDim.x * 256 * 8;
    for (; i < n; i += stride) {
        float4 a = *(const float4*)(s + i);
        float4 b = *(const float4*)(s + i + 4);
        __half2 h[4] = { __floats2half2_rn(a.x, a.y), __floats2half2_rn(a.z, a.w),
                         __floats2half2_rn(b.x, b.y), __floats2half2_rn(b.z, b.w) };
        *(uint2*)(d + i)     = *(uint2*)&h[0];
        *(uint2*)(d + i + 4) = *(uint2*)&h[2];
    }
}

// ---------------- fp16 tensor-core GEMM: cp.async + ldmatrix, BK=64 ----------
// C = op( A @ B (+ bias) ). A half [M,K] row-major (row-pred), B half [K,N].
// Output: Ch!=null -> fp16; else fp32 (fuse==2 residual add).
// Invariants: K%BK==0, N%BN==0, 16B-aligned rows. Dynamic smem.
template<int BM, int BN, int BK, int WM, int WN>
__global__ void __launch_bounds__(WM * WN * 32)
gemm_tc(const __half* __restrict__ A, int lda,
        const __half* __restrict__ Bm, int ldb,
        const float* __restrict__ bias,
        float* __restrict__ C, __half* __restrict__ Ch, int ldc,
        int M, int N, int K, int fuse)
{
    constexpr int NTHREADS = WM * WN * 32;
    constexpr int MT = (BM / WM) / 16;
    constexpr int NT = (BN / WN) / 8;
    constexpr int A_IT = BM * BK / (NTHREADS * 8);
    constexpr int B_IT = BK * BN / (NTHREADS * 8);
    constexpr int AW   = BK / 2;
    constexpr int ASTR = AW + 4;          // 36 words (BK=64): conflict-free
    constexpr int BSTR = BN / 2 + 4;      // 68 words: conflict-free trans-ldsm
    constexpr int ASZ = BM * ASTR;
    constexpr int BSZ = BK * BSTR;

    extern __shared__ unsigned gsm[];
    unsigned* As = gsm;
    unsigned* Bs = gsm + 2 * ASZ;

    int r0 = blockIdx.y * BM;
    int c0 = blockIdx.x * BN;
    int tid  = threadIdx.x;
    int wid  = tid >> 5, lane = tid & 31;
    int wm   = wid / WN, wn = wid % WN;
    int q    = lane >> 2, r = lane & 3;

    unsigned asBase = (unsigned)__cvta_generic_to_shared(As);
    unsigned bsBase = (unsigned)__cvta_generic_to_shared(Bs);
    unsigned aoff = (((lane & 15) * ASTR + (lane >> 4) * 4) << 2);
    int mi = lane >> 3;
    unsigned boff = ((((lane & 7) + (mi & 1) * 8) * BSTR + (mi >> 1) * 4) << 2);

    float acc[MT][NT][4];
    #pragma unroll
    for (int i = 0; i < MT; i++)
        #pragma unroll
        for (int j = 0; j < NT; j++)
            #pragma unroll
            for (int t = 0; t < 4; t++) acc[i][j][t] = 0.f;

    auto loadTile = [&](int k0, int buf) {
        #pragma unroll
        for (int it = 0; it < A_IT; it++) {
            int idx = (tid + it * NTHREADS) * 8;
            int m = idx / BK, kk = idx % BK;
            bool p = (r0 + m) < M;
            int row = p ? (r0 + m) : 0;
            cpa16(asBase + ((buf * ASZ + m * ASTR + (kk >> 1)) << 2),
                  A + (long long)row * lda + k0 + kk, p);
        }
        #pragma unroll
        for (int it = 0; it < B_IT; it++) {
            int idx = (tid + it * NTHREADS) * 8;
            int kk = idx / BN, n = idx % BN;
            cpa16(bsBase + ((buf * BSZ + kk * BSTR + (n >> 1)) << 2),
                  Bm + (long long)(k0 + kk) * ldb + c0 + n, true);
        }
        CP_COMMIT();
    };

    int T = K / BK;
    loadTile(0, 0);

    for (int t = 0; t < T; t++) {
        if (t + 1 < T) {
            loadTile((t + 1) * BK, (t + 1) & 1);
            CP_WAIT(1);
        } else {
            CP_WAIT(0);
        }
        __syncthreads();

        unsigned aB = asBase + ((t & 1) * ASZ << 2);
        unsigned bB = bsBase + ((t & 1) * BSZ << 2);
        int nb_w = wn * (BN / WN) / 2;

        #pragma unroll
        for (int kw = 0; kw < AW; kw += 8) {
            unsigned af[MT][4];
            unsigned bf[NT][2];
            #pragma unroll
            for (int i = 0; i < MT; i++) {
                int m = wm * (BM / WM) + i * 16;
                ldsm_x4(af[i][0], af[i][1], af[i][2], af[i][3],
                        aB + ((m * ASTR + kw) << 2) + aoff);
            }
            int kk = kw * 2;
            #pragma unroll
            for (int jj = 0; jj < NT / 2; jj++) {
                ldsm_x4t(bf[2 * jj][0], bf[2 * jj][1],
                         bf[2 * jj + 1][0], bf[2 * jj + 1][1],
                         bB + ((kk * BSTR + nb_w + jj * 8) << 2) + boff);
            }
            #pragma unroll
            for (int i = 0; i < MT; i++)
                #pragma unroll
                for (int j = 0; j < NT; j++)
                    MMA_F16(acc[i][j], af[i], bf[j]);
        }
        __syncthreads();
    }

    // ---- epilogue: vectorized paired stores (cols r*2, r*2+1 adjacent) ----
    #pragma unroll
    for (int i = 0; i < MT; i++) {
        #pragma unroll
        for (int j = 0; j < NT; j++) {
            #pragma unroll
            for (int h = 0; h < 2; h++) {           // h=0 -> t{0,1}, h=1 -> t{2,3}
                int row = r0 + wm * (BM / WM) + i * 16 + q + h * 8;
                if (row >= M) continue;
                int col = c0 + wn * (BN / WN) + j * 8 + r * 2;
                float v0 = acc[i][j][h * 2 + 0];
                float v1 = acc[i][j][h * 2 + 1];
                if (bias) { v0 += bias[col]; v1 += bias[col + 1]; }
                if (fuse == 1) {
                    v0 = 0.5f * v0 * (1.f + erff(v0 * 0.70710678118654752f));
                    v1 = 0.5f * v1 * (1.f + erff(v1 * 0.70710678118654752f));
                }
                long long off = (long long)row * ldc + col;
                if (Ch) {
                    __half2 hv = __floats2half2_rn(v0, v1);
                    *(__half2*)(Ch + off) = hv;
                } else {
                    if (fuse == 2) {
                        float2 old = *(float2*)(C + off);
                        v0 += old.x; v1 += old.y;
                    }
                    float2 nv = make_float2(v0, v1);
                    *(float2*)(C + off) = nv;
                }
            }
        }
    }
}

// ---------------- fused flash attention (round-15 proven) ---------------------
#define BQ   128
#define BKC  64
#define DW   (HDIM / 2)
#define QSTRh (DW + 4)
#define PW   (BKC / 2)
#define PSTRh (PW + 4)

__device__ __forceinline__ unsigned f2h2(float x, float y) {
    __half2 h = __floats2half2_rn(x, y);
    return *reinterpret_cast<unsigned*>(&h);
}

__global__ void __launch_bounds__(256)
flash_attn_kernel(const __half* __restrict__ QKV, __half* __restrict__ O)
{
    extern __shared__ unsigned fa_sm[];
    unsigned* sQ = fa_sm;
    unsigned* sK = sQ + BQ  * QSTRh;
    unsigned* sV = sK + BKC * QSTRh;
    unsigned* sP = sV + BKC * QSTRh;

    int z  = blockIdx.z;
    int b  = z / HEADS, h = z % HEADS;
    int q0 = blockIdx.y * BQ;

    const __half* Qg = QKV + (long long)b * SEQ * (3 * DIM) + h * HDIM;
    const __half* Kg = Qg + DIM;
    const __half* Vg = Qg + 2 * DIM;

    int tid  = threadIdx.x;
    int wid  = tid >> 5, lane = tid & 31;
    int qr   = lane >> 2, r = lane & 3;
    int mrow = wid * 16;

    unsigned sQb = (unsigned)__cvta_generic_to_shared(sQ);
    unsigned sKb = (unsigned)__cvta_generic_to_shared(sK);
    unsigned sVb = (unsigned)__cvta_generic_to_shared(sV);
    unsigned sPb = (unsigned)__cvta_generic_to_shared(sP);
    unsigned qoff = (((lane & 15) * QSTRh + (lane >> 4) * 4) << 2);
    unsigned koff = (((lane & 7)  * QSTRh + ((lane >> 3) & 1) * 4) << 2);
    unsigned poff = (((lane & 15) * PSTRh + (lane >> 4) * 4) << 2);
    unsigned voff = ((((lane & 7) + ((lane >> 3) & 1) * 8) * QSTRh) << 2);

    #pragma unroll
    for (int it = 0; it < BQ * HDIM / (256 * 8); it++) {
        int idx = (tid + it * 256) * 8;
        int m = idx / HDIM, d = idx % HDIM;
        uint4 v = make_uint4(0u, 0u, 0u, 0u);
        if (q0 + m < SEQ)
            v = *(const uint4*)(Qg + (long long)(q0 + m) * (3 * DIM) + d);
        *(uint4*)&sQ[m * QSTRh + (d >> 1)] = v;
    }

    float acc_O[8][4];
    #pragma unroll
    for (int j = 0; j < 8; j++)
        #pragma unroll
        for (int t = 0; t < 4; t++) acc_O[j][t] = 0.f;
    float mstate[2] = { -3.0e38f, -3.0e38f };
    float lstate[2] = { 0.f, 0.f };

    const int nchunks = (SEQ + BKC - 1) / BKC;
    for (int c = 0; c < nchunks; c++) {
        int kb = c * BKC;
        __syncthreads();

        #pragma unroll
        for (int it = 0; it < BKC * HDIM / (256 * 8); it++) {
            int idx = (tid + it * 256) * 8;
            int n = idx / HDIM, d = idx % HDIM;
            uint4 v = make_uint4(0u, 0u, 0u, 0u);
            if (kb + n < SEQ)
                v = *(const uint4*)(Kg + (long long)(kb + n) * (3 * DIM) + d);
            *(uint4*)&sK[n * QSTRh + (d >> 1)] = v;
        }
        #pragma unroll
        for (int it = 0; it < BKC * HDIM / (256 * 8); it++) {
            int idx = (tid + it * 256) * 8;
            int n = idx / HDIM, d = idx % HDIM;
            uint4 v = make_uint4(0u, 0u, 0u, 0u);
            if (kb + n < SEQ)
                v = *(const uint4*)(Vg + (long long)(kb + n) * (3 * DIM) + d);
            *(uint4*)&sV[n * QSTRh + (d >> 1)] = v;
        }
        __syncthreads();

        float acc_S[8][4];
        #pragma unroll
        for (int j = 0; j < 8; j++)
            #pragma unroll
            for (int t = 0; t < 4; t++) acc_S[j][t] = 0.f;

        #pragma unroll
        for (int kw = 0; kw < DW; kw += 8) {
            unsigned a[4];
            ldsm_x4(a[0], a[1], a[2], a[3],
                    sQb + ((mrow * QSTRh + kw) << 2) + qoff);
            #pragma unroll
            for (int j = 0; j < 8; j++) {
                unsigned bb[2];
                ldsm_x2(bb[0], bb[1],
                        sKb + (((j * 8) * QSTRh + kw) << 2) + koff);
                MMA_F16(acc_S[j], a, bb);
            }
        }

        float cmax[2] = { -3.0e38f, -3.0e38f };
        #pragma unroll
        for (int j = 0; j < 8; j++)
            #pragma unroll
            for (int t = 0; t < 4; t++) {
                int col = j * 8 + r * 2 + (t & 1);
                if (kb + col >= SEQ) acc_S[j][t] = -3.0e38f;
                cmax[t >> 1] = fmaxf(cmax[t >> 1], acc_S[j][t]);
            }
        #pragma unroll
        for (int o = 1; o <= 2; o <<= 1) {
            cmax[0] = fmaxf(cmax[0], __shfl_xor_sync(0xffffffffu, cmax[0], o));
            cmax[1] = fmaxf(cmax[1], __shfl_xor_sync(0xffffffffu, cmax[1], o));
        }
        float mnew[2]  = { fmaxf(mstate[0], cmax[0]), fmaxf(mstate[1], cmax[1]) };
        float scale[2] = { __expf(mstate[0] - mnew[0]), __expf(mstate[1] - mnew[1]) };
        float csum[2] = { 0.f, 0.f };
        #pragma unroll
        for (int j = 0; j < 8; j++)
            #pragma unroll
            for (int t = 0; t < 4; t++) {
                float p = __expf(acc_S[j][t] - mnew[t >> 1]);
                acc_S[j][t] = p;
                csum[t >> 1] += p;
            }
        #pragma unroll
        for (int o = 1; o <= 2; o <<= 1) {
            csum[0] += __shfl_xor_sync(0xffffffffu, csum[0], o);
            csum[1] += __shfl_xor_sync(0xffffffffu, csum[1], o);
        }
        lstate[0] = lstate[0] * scale[0] + csum[0];
        lstate[1] = lstate[1] * scale[1] + csum[1];
        mstate[0] = mnew[0];
        mstate[1] = mnew[1];
        #pragma unroll
        for (int j = 0; j < 8; j++)
            #pragma unroll
            for (int t = 0; t < 4; t++)
                acc_O[j][t] *= scale[t >> 1];

        #pragma unroll
        for (int j = 0; j < 8; j++) {
            sP[(mrow + qr    ) * PSTRh + j * 4 + r] = f2h2(acc_S[j][0], acc_S[j][1]);
            sP[(mrow + qr + 8) * PSTRh + j * 4 + r] = f2h2(acc_S[j][2], acc_S[j][3]);
        }
        __syncwarp();

        #pragma unroll
        for (int kw = 0; kw < PW; kw += 8) {
            unsigned a[4];
            ldsm_x4(a[0], a[1], a[2], a[3],
                    sPb + ((mrow * PSTRh + kw) << 2) + poff);
            #pragma unroll
            for (int j = 0; j < 8; j++) {
                unsigned bb[2];
                ldsm_x2t(bb[0], bb[1],
                         sVb + (((kw * 2) * QSTRh + j * 4) << 2) + voff);
                MMA_F16(acc_O[j], a, bb);
            }
        }
    }

    float inv[2] = { 1.f / lstate[0], 1.f / lstate[1] };
    #pragma unroll
    for (int j = 0; j < 8; j++)
        #pragma unroll
        for (int h2 = 0; h2 < 2; h2++) {
            int row = q0 + mrow + qr + h2 * 8;
            if (row >= SEQ) continue;
            int col = j * 8 + r * 2;
            __half2 hv = __floats2half2_rn(acc_O[j][h2 * 2] * inv[h2],
                                           acc_O[j][h2 * 2 + 1] * inv[h2]);
            *(__half2*)(O + ((long long)b * SEQ + row) * DIM + h * HDIM + col) = hv;
        }
}

// ---------------- reductions -------------------------------------------------
__device__ __forceinline__ float blockReduceSum(float v, volatile float* sh) {
    int lane = threadIdx.x & 31, w = threadIdx.x >> 5;
    #pragma unroll
    for (int o = 16; o; o >>= 1) v += __shfl_down_sync(0xffffffffu, v, o);
    if (lane == 0) sh[w] = v;
    __syncthreads();
    if (threadIdx.x < 32) {
        v = (threadIdx.x < 8) ? sh[threadIdx.x] : 0.f;
        #pragma unroll
        for (int o = 4; o; o >>= 1) v += __shfl_down_sync(0xffffffffu, v, o);
        if (lane == 0) sh[0] = v;
    }
    __syncthreads();
    return sh[0];
}

// ---------------- layernorm (fp32 in, fp16 out) -------------------------------
__global__ void __launch_bounds__(256)
layernorm_kernel(const float* __restrict__ X, const float* __restrict__ g,
                 const float* __restrict__ b, __half* __restrict__ Y)
{
    long long row = blockIdx.x;
    const float* x = X + row * DIM;
    __shared__ float sh0[8], sh1[8];
    float v0 = x[threadIdx.x], v1 = x[threadIdx.x + 256], v2 = x[threadIdx.x + 512];
    float sum  = blockReduceSum(v0 + v1 + v2, sh0);
    float sum2 = blockReduceSum(v0 * v0 + v1 * v1 + v2 * v2, sh1);
    float m   = sum * (1.f / DIM);
    float var = sum2 * (1.f / DIM) - m * m;
    float inv = rsqrtf(var + 1e-5f);
    __half* y = Y + row * DIM;
    #pragma unroll
    for (int i = 0; i < 3; i++) {
        int c = threadIdx.x + i * 256;
        float xv = (i == 0) ? v0 : (i == 1) ? v1 : v2;
        y[c] = __float2half_rn((xv - m) * inv * g[c] + b[c]);
    }
}

// ---------------- patchify (fp16 out) -----------------------------------------
__global__ void __launch_bounds__(256)
patchify_kernel(const float* __restrict__ img)
{
    int idx = blockIdx.x * 256 + threadIdx.x;
    if (idx >= BATCH * NPATCH * PDIM) return;
    int pd = idx % PDIM;
    int t  = idx / PDIM;
    int patch = t % NPATCH;
    int b     = t / NPATCH;
    int c  = pd % 3;
    int pp = pd / 3;
    int p2 = pp % PSZ, p1 = pp / PSZ;
    int wx = patch % HP, hy = patch / HP;
    g_Ph[idx] = __float2half_rn(
        img[(((long long)b * 3 + c) * IMGH + hy * PSZ + p1) * IMGH + wx * PSZ + p2]);
}

// ---------------- assemble: cls + pos add (fp32) ------------------------------
__global__ void __launch_bounds__(256)
assemble_kernel(const float* __restrict__ emb, const float* __restrict__ cls,
                const float* __restrict__ pos)
{
    int idx = blockIdx.x * 256 + threadIdx.x;
    if (idx >= BATCH * SEQ * DIM) return;
    int d = idx % DIM;
    int t = idx / DIM;
    int s = t % SEQ;
    int b = t / SEQ;
    float v;
    if (s == 0) v = cls[d] + pos[d];
    else        v = emb[((long long)b * NPATCH + (s - 1)) * DIM + d] + pos[(long long)s * DIM + d];
    g_X[idx] = v;
}

// ---------------- output: drop cls token --------------------------------------
__global__ void __launch_bounds__(256)
output_kernel(float* __restrict__ out)
{
    int idx = blockIdx.x * 256 + threadIdx.x;
    if (idx >= BATCH * NPATCH * DIM) return;
    int d = idx % DIM;
    int t = idx / DIM;
    int s = t % NPATCH;
    int b = t / NPATCH;
    out[idx] = g_X[((long long)b * SEQ + (s + 1)) * DIM + d];
}

// ---------------- host driver -------------------------------------------------
extern "C" void kernel_launch(void* const* d_in, const int* in_sizes, int n_in,
                              void* d_out, int out_size)
{
    const float* img   = (const float*)d_in[0];
    const float* pos   = (const float*)d_in[1];
    const float* cls   = (const float*)d_in[2];
    const float* pw    = (const float*)d_in[3];
    const float* pb    = (const float*)d_in[4];
    const float* ln1g  = (const float*)d_in[5];
    const float* ln1b  = (const float*)d_in[6];
    const float* qkvw  = (const float*)d_in[7];
    const float* outw  = (const float*)d_in[8];
    const float* outb  = (const float*)d_in[9];
    const float* ln2g  = (const float*)d_in[10];
    const float* ln2b  = (const float*)d_in[11];
    const float* ff1w  = (const float*)d_in[12];
    const float* ff1b  = (const float*)d_in[13];
    const float* ff2w  = (const float*)d_in[14];
    const float* ff2b  = (const float*)d_in[15];
    float* out = (float*)d_out;

    float  *pX, *pYf;
    __half *pYh, *pQKV, *pO, *pH, *pP, *pWw;
    cudaGetSymbolAddress((void**)&pX,   g_X);
    cudaGetSymbolAddress((void**)&pYf,  g_Yf);
    cudaGetSymbolAddress((void**)&pYh,  g_Yh);
    cudaGetSymbolAddress((void**)&pQKV, g_QKVh);
    cudaGetSymbolAddress((void**)&pO,   g_Oh);
    cudaGetSymbolAddress((void**)&pH,   g_Hh);
    cudaGetSymbolAddress((void**)&pP,   g_Ph);
    cudaGetSymbolAddress((void**)&pWw,  g_W16);

    const int Mfull = BATCH * SEQ;
    const int Mpat  = BATCH * NPATCH;

    const int GM_SMEM   = (2 * 128 * 36 + 2 * 64 * 68) * 4;  // 71680 (BM=128)
    const int GM_SMEM64 = (2 * 64 * 36 + 2 * 64 * 68) * 4;   // 53248 (BM=64)
    const int FA_SMEM = ((BQ + BKC + BKC) * QSTRh + BQ * PSTRh) * 4;

    static int attr_done = 0;
    if (!attr_done) {
        cudaFuncSetAttribute((const void*)gemm_tc<128,128,64,2,4>,
                             cudaFuncAttributeMaxDynamicSharedMemorySize, GM_SMEM);
        cudaFuncSetAttribute((const void*)gemm_tc<64,128,64,2,4>,
                             cudaFuncAttributeMaxDynamicSharedMemorySize, GM_SMEM64);
        cudaFuncSetAttribute((const void*)flash_attn_kernel,
                             cudaFuncAttributeMaxDynamicSharedMemorySize, FA_SMEM);
        attr_done = 1;
    }

    auto grid128 = [](int M, int N, int Z) {
        return dim3((N + 127) / 128, (M + 127) / 128, Z);
    };
    auto grid64 = [](int M, int N, int Z) {
        return dim3((N + 127) / 128, (M + 63) / 64, Z);
    };
    auto cgrid = [](int n) { int g = (n / 8 + 255) / 256; return g > 2048 ? 2048 : g; };

    // 0) convert weights to fp16
    f2h_kernel<<<cgrid(SZ_PW),  256>>>(pw,   pWw + OFF_PW,  SZ_PW);
    f2h_kernel<<<cgrid(SZ_QKV), 256>>>(qkvw, pWw + OFF_QKV, SZ_QKV);
    f2h_kernel<<<cgrid(SZ_OUT), 256>>>(outw, pWw + OFF_OUT, SZ_OUT);
    f2h_kernel<<<cgrid(SZ_FF1), 256>>>(ff1w, pWw + OFF_FF1, SZ_FF1);
    f2h_kernel<<<cgrid(SZ_FF2), 256>>>(ff2w, pWw + OFF_FF2, SZ_FF2);

    // 1) patchify + patch embed + assemble
    patchify_kernel<<<(BATCH * NPATCH * PDIM + 255) / 256, 256>>>(img);
    gemm_tc<128,128,64,2,4><<<grid128(Mpat, DIM, 1), 256, GM_SMEM>>>(
        pP, PDIM,  pWw + OFF_PW, DIM,  pb,
        pYf, nullptr, DIM,  Mpat, DIM, PDIM, 0);
    assemble_kernel<<<(BATCH * SEQ * DIM + 255) / 256, 256>>>(pYf, cls, pos);

    // 2) transformer layers
    for (int l = 0; l < DEPTH; l++) {
        const __half* wqkv = pWw + OFF_QKV + (long long)l * DIM * 3 * DIM;
        const __half* wo   = pWw + OFF_OUT + (long long)l * DIM * DIM;
        const __half* w1   = pWw + OFF_FF1 + (long long)l * DIM * MLPD;
        const __half* w2   = pWw + OFF_FF2 + (long long)l * MLPD * DIM;
        const float* bo = outb + (long long)l * DIM;
        const float* b1 = ff1b + (long long)l * MLPD;
        const float* b2 = ff2b + (long long)l * DIM;

        layernorm_kernel<<<Mfull, 256>>>(pX, ln1g + (long long)l * DIM,
                                         ln1b + (long long)l * DIM, pYh);
        // QKV (N=2304, 666 CTAs -> BM=128)
        gemm_tc<128,128,64,2,4><<<grid128(Mfull, 3 * DIM, 1), 256, GM_SMEM>>>(
            pYh, DIM,  wqkv, 3 * DIM,  nullptr,
            nullptr, pQKV, 3 * DIM,  Mfull, 3 * DIM, DIM, 0);
        {
            dim3 g(1, (SEQ + BQ - 1) / BQ, BATCH * HEADS);
            flash_attn_kernel<<<g, 256, FA_SMEM>>>(pQKV, pO);
        }
        // proj (N=768 -> BM=64 for wave balance: 438 CTAs)
        gemm_tc<64,128,64,2,4><<<grid64(Mfull, DIM, 1), 256, GM_SMEM64>>>(
            pO, DIM,  wo, DIM,  bo,
            pX, nullptr, DIM,  Mfull, DIM, DIM, 2);
        layernorm_kernel<<<Mfull, 256>>>(pX, ln2g + (long long)l * DIM,
                                         ln2b + (long long)l * DIM, pYh);
        // FF1 (N=3072, 888 CTAs -> BM=128)
        gemm_tc<128,128,64,2,4><<<grid128(Mfull, MLPD, 1), 256, GM_SMEM>>>(
            pYh, DIM,  w1, MLPD,  b1,
            nullptr, pH, MLPD,  Mfull, MLPD, DIM, 1);
        // FF2 (N=768 -> BM=64: 438 CTAs)
        gemm_tc<64,128,64,2,4><<<grid64(Mfull, DIM, 1), 256, GM_SMEM64>>>(
            pH, MLPD,  w2, DIM,  b2,
            pX, nullptr, DIM,  Mfull, DIM, MLPD, 2);
    }

    // 3) drop cls token -> output
    output_kernel<<<(BATCH * NPATCH * DIM + 255) / 256, 256>>>(out);
}